// round 13
// baseline (speedup 1.0000x reference)
#include <cuda_runtime.h>
#include <cuda_fp16.h>
#include <cstdint>
#include <cstddef>

// ---------------------------------------------------------------------------
// SelfAttention on sm_103, mma.sync fp16, fp32 accumulate everywhere.
// R13: revert R12's 128x128 tile (regression: lost 3-CTA residency + tail
// wave). Back to R11's 64x128 / 3-CTA-resident GEMM, with kchunk widened
// 32->64 (smem stride 144B, conflict-free: 144/16=9 coprime 8) to HALVE the
// per-ktile cp.async-wait + syncthreads count (the R11 bubble source).
// MMA sequence identical -> bit-identical results (rel_err 7.07e-4).
// ---------------------------------------------------------------------------

#define Tn     2048
#define Cn     2048
#define QKVW   3072          // (16 + 2*4) * 128
#define ROWS   4096          // B*T
#define GK     2048          // K dim of both big GEMMs

typedef __half f16;

__device__ __align__(16) float g_qkv[(size_t)ROWS * QKVW];
__device__ __align__(16) f16  g_xh[(size_t)ROWS * GK];
__device__ __align__(16) f16  g_wah[(size_t)QKVW * GK];
__device__ __align__(16) f16  g_wph[(size_t)Cn * GK];
__device__ __align__(16) f16  g_qh[(size_t)2 * 16 * Tn * 128];
__device__ __align__(16) f16  g_kh[(size_t)2 * 4 * Tn * 128];
__device__ __align__(16) f16  g_vth[(size_t)2 * 4 * 128 * Tn];
__device__ __align__(16) f16  g_yh[(size_t)ROWS * Cn];

// 1/sqrt(128) * log2(e): softmax scale + exp->exp2, folded into q
#define QK_SCALE (0.08838834764831845f * 1.4426950408889634f)

// ============================ helpers =======================================
__device__ __forceinline__ float ex2f(float x) {
    float r;
    asm("ex2.approx.ftz.f32 %0, %1;" : "=f"(r) : "f"(x));
    return r;
}
__device__ __forceinline__ uint32_t pkh2(float lo, float hi) {
    __half2 h = __floats2half2_rn(lo, hi);
    return *reinterpret_cast<uint32_t*>(&h);
}
__device__ __forceinline__ void mma_f32a(float (&d)[4], const uint32_t (&a)[4],
                                         const uint32_t* b) {
    asm volatile(
        "mma.sync.aligned.m16n8k16.row.col.f32.f16.f16.f32 "
        "{%0,%1,%2,%3}, {%4,%5,%6,%7}, {%8,%9}, {%0,%1,%2,%3};"
        : "+f"(d[0]), "+f"(d[1]), "+f"(d[2]), "+f"(d[3])
        : "r"(a[0]), "r"(a[1]), "r"(a[2]), "r"(a[3]), "r"(b[0]), "r"(b[1]));
}
__device__ __forceinline__ void ldsm4(uint32_t* r, uint32_t a) {
    asm volatile("ldmatrix.sync.aligned.m8n8.x4.shared.b16 {%0,%1,%2,%3}, [%4];"
                 : "=r"(r[0]), "=r"(r[1]), "=r"(r[2]), "=r"(r[3]) : "r"(a));
}
__device__ __forceinline__ uint32_t smem_u32(const void* p) {
    uint32_t a;
    asm("{ .reg .u64 t; cvta.to.shared.u64 t, %1; cvt.u32.u64 %0, t; }"
        : "=r"(a) : "l"(p));
    return a;
}
#define CP16(dst, src) \
    asm volatile("cp.async.cg.shared.global [%0], [%1], 16;" \
                 :: "r"(dst), "l"(src) : "memory")
#define CPCOMMIT() asm volatile("cp.async.commit_group;" ::: "memory")
#define CPWAIT1()  asm volatile("cp.async.wait_group 1;" ::: "memory")
#define CPWAIT0()  asm volatile("cp.async.wait_group 0;" ::: "memory")

// ---------------------------------------------------------------------------
// convert x -> fp16
// ---------------------------------------------------------------------------
__global__ __launch_bounds__(256) void splitx_kernel(const float* __restrict__ x) {
    size_t i = ((size_t)blockIdx.x * 256 + threadIdx.x) * 4;
    float4 v = *(const float4*)(x + i);
    uint32_t p0 = pkh2(v.x, v.y), p1 = pkh2(v.z, v.w);
    *(uint2*)(g_xh + i) = make_uint2(p0, p1);
}

// ---------------------------------------------------------------------------
// transpose weights to fp16: in [2048][Ccols] fp32 -> [Ccols][2048]
// ---------------------------------------------------------------------------
__global__ __launch_bounds__(256) void wsplit_kernel(
    const float* __restrict__ in, f16* __restrict__ hi, int Ccols)
{
    __shared__ float tb[32][33];
    const int bx = blockIdx.x * 32, by = blockIdx.y * 32;
    const int tx = threadIdx.x, ty = threadIdx.y;
#pragma unroll
    for (int j = 0; j < 32; j += 8)
        tb[ty + j][tx] = in[(size_t)(by + ty + j) * Ccols + bx + tx];
    __syncthreads();
#pragma unroll
    for (int j = 0; j < 32; j += 8) {
        float v = tb[tx][ty + j];
        hi[(size_t)(bx + ty + j) * GK + by + tx] = __float2half_rn(v);
    }
}

// ---------------------------------------------------------------------------
// fp16 1-term GEMM: C[M,N] = A @ B^T, f32 accumulate.
// CTA tile 64x128, kchunk 64, cp.async double buffer, 8 warps (2m x 4n),
// warp tile 32x32. smem stage (stride 144B): A@0 (64x144=9216),
// B@9216 (128x144=18432); stage 27648, x2 = 55296 -> 3 CTAs/SM (80 regs).
// ---------------------------------------------------------------------------
#define GSTR 144
#define GS_A 0
#define GS_B 9216
#define GS_STAGE 27648
#define GSM (2 * GS_STAGE)

__global__ __launch_bounds__(256, 2) void hgemm1_kernel(
    const f16* __restrict__ A, const f16* __restrict__ B,
    float* __restrict__ C, int N)
{
    extern __shared__ char sm[];
    const uint32_t sb = smem_u32(sm);
    const int tid = threadIdx.x;
    const int lane = tid & 31, wid = tid >> 5;
    const int lg = lane >> 2, tq = lane & 3;
    const int mi = wid & 1, ni = wid >> 1;
    const size_t m0 = (size_t)blockIdx.y * 64, n0 = (size_t)blockIdx.x * 128;

    const uint32_t abase =
        (uint32_t)(GS_A + (mi * 32 + (lane & 15)) * GSTR + (lane >> 4) * 16);
    const uint32_t bbase =
        (uint32_t)(GS_B + (ni * 32 + (lane & 7) + ((lane >> 4) * 8)) * GSTR +
                   ((lane >> 3) & 1) * 16);

    // loaders (per 64-k stage): A 64 rows x 128B -> 32B/thread (2 CP16);
    //                           B 128 rows x 128B -> 64B/thread (4 CP16)
    const int arow = tid >> 2, aq = tid & 3;          // A: row, 32B quarter
    const int brow = tid >> 1, bh = tid & 1;          // B: row, 64B half
    const f16* pA = A + (m0 + arow) * GK + aq * 16;
    const f16* pB = B + (n0 + brow) * GK + bh * 32;
    const uint32_t sdA = sb + GS_A + arow * GSTR + aq * 32;
    const uint32_t sdB = sb + GS_B + brow * GSTR + bh * 64;

    float c[2][4][4];
#pragma unroll
    for (int a = 0; a < 2; a++)
#pragma unroll
        for (int b = 0; b < 4; b++)
#pragma unroll
            for (int d = 0; d < 4; d++) c[a][b][d] = 0.f;

    {
        CP16(sdA,      pA);
        CP16(sdA + 16, pA + 8);
        CP16(sdB,      pB);
        CP16(sdB + 16, pB + 8);
        CP16(sdB + 32, pB + 16);
        CP16(sdB + 48, pB + 24);
        CPCOMMIT();
    }

#pragma unroll 1
    for (int kt = 0; kt < GK / 64; kt++) {
        const int s = kt & 1;
        if (kt + 1 < GK / 64) {
            uint32_t dA = sdA + (s ^ 1) * GS_STAGE;
            uint32_t dB = sdB + (s ^ 1) * GS_STAGE;
            size_t off = (size_t)(kt + 1) * 64;
            CP16(dA,      pA + off);
            CP16(dA + 16, pA + off + 8);
            CP16(dB,      pB + off);
            CP16(dB + 16, pB + off + 8);
            CP16(dB + 32, pB + off + 16);
            CP16(dB + 48, pB + off + 24);
            CPCOMMIT();
            CPWAIT1();
        } else {
            CPWAIT0();
        }
        __syncthreads();

        const uint32_t stg = sb + s * GS_STAGE;
#pragma unroll
        for (int kk = 0; kk < 4; kk++) {
            uint32_t ah[2][4];
#pragma unroll
            for (int mt = 0; mt < 2; mt++)
                ldsm4(ah[mt], stg + abase + mt * (16 * GSTR) + kk * 32);
            uint32_t bb[4][2];
#pragma unroll
            for (int p = 0; p < 2; p++)
                ldsm4(&bb[2 * p][0], stg + bbase + p * (16 * GSTR) + kk * 32);
#pragma unroll
            for (int mt = 0; mt < 2; mt++)
#pragma unroll
                for (int nt = 0; nt < 4; nt++) mma_f32a(c[mt][nt], ah[mt], bb[nt]);
        }
        __syncthreads();
    }

#pragma unroll
    for (int mt = 0; mt < 2; mt++) {
        size_t r0 = m0 + mi * 32 + mt * 16 + lg;
#pragma unroll
        for (int nt = 0; nt < 4; nt++) {
            size_t col = n0 + ni * 32 + nt * 8 + tq * 2;
            *(float2*)(C + r0 * N + col) = make_float2(c[mt][nt][0], c[mt][nt][1]);
            *(float2*)(C + (r0 + 8) * N + col) = make_float2(c[mt][nt][2], c[mt][nt][3]);
        }
    }
}

// ---------------------------------------------------------------------------
// RoPE + fp16: q (slots 0-3, scaled) -> g_qh; k (slot 4) -> g_kh
// ---------------------------------------------------------------------------
__global__ __launch_bounds__(256) void rope_split_kernel(
    const float* __restrict__ cosb, const float* __restrict__ sinb)
{
    int idx = blockIdx.x * 256 + threadIdx.x;     // ROWS*4*5*64
    int d = idx & 63;
    int rg = idx >> 6;
    int slot = rg % 5;
    int q5 = rg / 5;
    int grp = q5 & 3;
    int row = q5 >> 2;
    int b = row >> 11, t = row & (Tn - 1);

    const float* p = g_qkv + (size_t)row * QKVW + grp * 768 + slot * 128 + d;
    float x1 = p[0], x2 = p[64];
    float cc = cosb[t * 64 + d], ss = sinb[t * 64 + d];
    float o1 = x1 * cc - x2 * ss;
    float o2 = x1 * ss + x2 * cc;

    if (slot < 4) {
        o1 *= QK_SCALE; o2 *= QK_SCALE;
        int head = grp * 4 + slot;
        size_t base = ((size_t)(b * 16 + head) * Tn + t) * 128 + d;
        g_qh[base]      = __float2half_rn(o1);
        g_qh[base + 64] = __float2half_rn(o2);
    } else {
        size_t base = ((size_t)(b * 4 + grp) * Tn + t) * 128 + d;
        g_kh[base]      = __float2half_rn(o1);
        g_kh[base + 64] = __float2half_rn(o2);
    }
}

// ---------------------------------------------------------------------------
// v: transpose -> g_vth [b][g][d][t]
// ---------------------------------------------------------------------------
__global__ __launch_bounds__(256) void vsplit_kernel() {
    __shared__ float tb[32][33];
    const int bg = blockIdx.z;
    const int t0 = blockIdx.x * 32, d0 = blockIdx.y * 32;
    const int tx = threadIdx.x, ty = threadIdx.y;
    const int b = bg >> 2, grp = bg & 3;
#pragma unroll
    for (int j = 0; j < 32; j += 8)
        tb[ty + j][tx] = g_qkv[((size_t)b * Tn + t0 + ty + j) * QKVW +
                               grp * 768 + 640 + d0 + tx];
    __syncthreads();
#pragma unroll
    for (int j = 0; j < 32; j += 8) {
        float v = tb[tx][ty + j];
        size_t o = ((size_t)bg * 128 + d0 + ty + j) * Tn + t0 + tx;
        g_vth[o] = __float2half_rn(v);
    }
}

// ---------------------------------------------------------------------------
// Flash attention, plain fp16 inputs, f32 accumulate.
// CTA = (qb, h, b): 128 q rows, 8 warps x m16. Key tiles of 64.
// smem: Qh [128 x 272B], Kh [64 x 272B], Vth [128 d x 144B] = 70656 B.
// ---------------------------------------------------------------------------
#define AQ_H 0
#define AK_H 34816
#define AV_H 52224
#define ATT_SMEM 70656

__global__ __launch_bounds__(256, 1) void attn_kernel() {
    extern __shared__ char sm[];
    const uint32_t sb = smem_u32(sm);
    const int tid = threadIdx.x;
    const int lane = tid & 31, wid = tid >> 5;
    const int lg = lane >> 2, tq = lane & 3;
    const int qb = blockIdx.x, h = blockIdx.y, b = blockIdx.z;
    const int grp = h >> 2;

    const uint32_t qbase = sb + AQ_H + (wid * 16 + (lane & 15)) * 272 +
                           (lane >> 4) * 16;
    const uint32_t kbase = sb + AK_H + ((lane & 7) + ((lane >> 4) * 8)) * 272 +
                           ((lane >> 3) & 1) * 16;
    const uint32_t vbase = sb + AV_H + ((lane & 7) + ((lane >> 4) * 8)) * 144 +
                           ((lane >> 3) & 1) * 16;

    // load Q, 128 x 128 f16
    {
        const f16* qhp = g_qh + ((size_t)(b * 16 + h) * Tn + qb * 128) * 128;
#pragma unroll
        for (int it = 0; it < 8; it++) {
            int idx = it * 256 + tid;
            int r = idx >> 4, hx = idx & 15;
            *(uint4*)(sm + AQ_H + r * 272 + hx * 16) =
                *(const uint4*)(qhp + (size_t)r * 128 + hx * 8);
        }
    }

    float o[16][4];
#pragma unroll
    for (int i = 0; i < 16; i++)
#pragma unroll
        for (int j = 0; j < 4; j++) o[i][j] = 0.f;
    float m0 = __int_as_float(0xff800000), m1 = m0;
    float l0 = 0.f, l1 = 0.f;

    const f16* khp = g_kh + (size_t)(b * 4 + grp) * Tn * 128;
    const f16* vhp = g_vth + (size_t)(b * 4 + grp) * 128 * Tn;

#pragma unroll 1
    for (int kt = 0; kt < Tn / 64; kt++) {
        __syncthreads();
#pragma unroll
        for (int it = 0; it < 4; it++) {
            int idx = it * 256 + tid;
            int r = idx >> 4, hx = idx & 15;
            size_t go = ((size_t)kt * 64 + r) * 128 + hx * 8;
            *(uint4*)(sm + AK_H + r * 272 + hx * 16) = *(const uint4*)(khp + go);
        }
#pragma unroll
        for (int it = 0; it < 4; it++) {
            int idx = it * 256 + tid;
            int r = idx >> 3, hx = idx & 7;
            size_t go = (size_t)r * Tn + kt * 64 + hx * 8;
            *(uint4*)(sm + AV_H + r * 144 + hx * 16) = *(const uint4*)(vhp + go);
        }
        __syncthreads();

        // ---- S = Q Kh^T, f32 acc ----
        float s[8][4];
#pragma unroll
        for (int i = 0; i < 8; i++)
#pragma unroll
            for (int j = 0; j < 4; j++) s[i][j] = 0.f;

#pragma unroll
        for (int kk = 0; kk < 8; kk++) {
            uint32_t qah[4];
            ldsm4(qah, qbase + kk * 32);
            uint32_t kb[8][2];
#pragma unroll
            for (int p = 0; p < 4; p++)
                ldsm4(&kb[2 * p][0], kbase + p * (16 * 272) + kk * 32);
#pragma unroll
            for (int nt = 0; nt < 8; nt++) mma_f32a(s[nt], qah, kb[nt]);
        }

        // ---- online softmax (2 rows per lane: lg, lg+8) ----
        float mx0 = s[0][0], mx1 = s[0][2];
#pragma unroll
        for (int nt = 0; nt < 8; nt++) {
            mx0 = fmaxf(mx0, fmaxf(s[nt][0], s[nt][1]));
            mx1 = fmaxf(mx1, fmaxf(s[nt][2], s[nt][3]));
        }
        mx0 = fmaxf(mx0, __shfl_xor_sync(0xffffffffu, mx0, 1));
        mx0 = fmaxf(mx0, __shfl_xor_sync(0xffffffffu, mx0, 2));
        mx1 = fmaxf(mx1, __shfl_xor_sync(0xffffffffu, mx1, 1));
        mx1 = fmaxf(mx1, __shfl_xor_sync(0xffffffffu, mx1, 2));
        float mn0 = fmaxf(m0, mx0), mn1 = fmaxf(m1, mx1);
        float cr0 = ex2f(m0 - mn0), cr1 = ex2f(m1 - mn1);
        m0 = mn0; m1 = mn1;
        float sum0 = 0.f, sum1 = 0.f;
#pragma unroll
        for (int nt = 0; nt < 8; nt++) {
            s[nt][0] = ex2f(s[nt][0] - mn0);
            s[nt][1] = ex2f(s[nt][1] - mn0);
            s[nt][2] = ex2f(s[nt][2] - mn1);
            s[nt][3] = ex2f(s[nt][3] - mn1);
            sum0 += s[nt][0] + s[nt][1];
            sum1 += s[nt][2] + s[nt][3];
        }
        sum0 += __shfl_xor_sync(0xffffffffu, sum0, 1);
        sum0 += __shfl_xor_sync(0xffffffffu, sum0, 2);
        sum1 += __shfl_xor_sync(0xffffffffu, sum1, 1);
        sum1 += __shfl_xor_sync(0xffffffffu, sum1, 2);
        l0 = l0 * cr0 + sum0;
        l1 = l1 * cr1 + sum1;
#pragma unroll
        for (int nt = 0; nt < 16; nt++) {
            o[nt][0] *= cr0; o[nt][1] *= cr0;
            o[nt][2] *= cr1; o[nt][3] *= cr1;
        }

        // ---- O += Ph Vh, f32 acc ----
#pragma unroll
        for (int kk = 0; kk < 4; kk++) {
            uint32_t ph[4];
#pragma unroll
            for (int q2 = 0; q2 < 2; q2++) {
                ph[2 * q2]     = pkh2(s[2 * kk + q2][0], s[2 * kk + q2][1]);
                ph[2 * q2 + 1] = pkh2(s[2 * kk + q2][2], s[2 * kk + q2][3]);
            }
#pragma unroll
            for (int blk = 0; blk < 2; blk++) {
                uint32_t vb[8][2];
#pragma unroll
                for (int p = 0; p < 4; p++)
                    ldsm4(&vb[2 * p][0], vbase + (blk * 64 + p * 16) * 144 + kk * 32);
#pragma unroll
                for (int j = 0; j < 8; j++) mma_f32a(o[blk * 8 + j], ph, vb[j]);
            }
        }
    }

    // ---- epilogue: y = O / l -> fp16 ----
    float i0 = 1.f / l0, i1 = 1.f / l1;
    size_t row0 = (size_t)b * Tn + qb * 128 + wid * 16 + lg;
#pragma unroll
    for (int nt = 0; nt < 16; nt++) {
        int col = h * 128 + nt * 8 + tq * 2;
        *(uint32_t*)(g_yh + row0 * Cn + col) =
            pkh2(o[nt][0] * i0, o[nt][1] * i0);
        *(uint32_t*)(g_yh + (row0 + 8) * Cn + col) =
            pkh2(o[nt][2] * i1, o[nt][3] * i1);
    }
}

// ---------------------------------------------------------------------------
extern "C" void kernel_launch(void* const* d_in, const int* in_sizes, int n_in,
                              void* d_out, int out_size) {
    const float* x      = (const float*)d_in[0];
    const float* cosb   = (const float*)d_in[1];
    const float* sinb   = (const float*)d_in[2];
    const float* w_attn = (const float*)d_in[3];
    const float* w_proj = (const float*)d_in[4];
    float* out = (float*)d_out;
    (void)in_sizes; (void)n_in; (void)out_size;

    (void)cudaFuncSetAttribute(hgemm1_kernel,
                               cudaFuncAttributeMaxDynamicSharedMemorySize, GSM);
    (void)cudaFuncSetAttribute(attn_kernel,
                               cudaFuncAttributeMaxDynamicSharedMemorySize, ATT_SMEM);

    float* qkvp = nullptr;
    f16 *xh, *wah, *wph, *yh;
    (void)cudaGetSymbolAddress((void**)&qkvp, g_qkv);
    (void)cudaGetSymbolAddress((void**)&xh, g_xh);
    (void)cudaGetSymbolAddress((void**)&wah, g_wah);
    (void)cudaGetSymbolAddress((void**)&wph, g_wph);
    (void)cudaGetSymbolAddress((void**)&yh, g_yh);

    // 0. fp16 conversions
    splitx_kernel<<<(ROWS * GK / 4) / 256, 256>>>(x);
    wsplit_kernel<<<dim3(QKVW / 32, GK / 32), dim3(32, 8)>>>(w_attn, wah, QKVW);
    wsplit_kernel<<<dim3(Cn / 32, GK / 32), dim3(32, 8)>>>(w_proj, wph, Cn);
    // 1. qkv = x @ w_attn (fp16, 64x128 tiles, kchunk 64)
    hgemm1_kernel<<<dim3(QKVW / 128, ROWS / 64), 256, GSM>>>(xh, wah, qkvp, QKVW);
    // 2. RoPE -> q, k (fp16)
    rope_split_kernel<<<(ROWS * 4 * 5 * 64) / 256, 256>>>(cosb, sinb);
    // 3. v transpose (fp16)
    vsplit_kernel<<<dim3(Tn / 32, 4, 8), dim3(32, 8)>>>();
    // 4. attention -> yh
    attn_kernel<<<dim3(Tn / 128, 16, 2), 256, ATT_SMEM>>>();
    // 5. out = y @ w_proj (fp16, 64x128 tiles, kchunk 64)
    hgemm1_kernel<<<dim3(Cn / 128, ROWS / 64), 256, GSM>>>(yh, wph, out, Cn);
}

// round 14
// speedup vs baseline: 1.2048x; 1.2048x over previous
#include <cuda_runtime.h>
#include <cuda_fp16.h>
#include <cstdint>
#include <cstddef>

// ---------------------------------------------------------------------------
// SelfAttention on sm_103, mma.sync fp16, fp32 accumulate everywhere.
// R14: R11 GEMM config (64x128 tile, kchunk 32, 3 CTAs/SM resident - the
// R12/R13 post-mortems proved residency dominates) + 3-stage cp.async ring:
// two loads in flight (wait_group 1) and ONE syncthreads per ktile instead
// of two. launch_bounds(256,3) pins regs <=85 so 3-CTA residency is
// guaranteed. MMA order identical -> rel_err exactly 7.065852e-4.
// Attention & prep byte-identical to R11 (best passing, 671.8us).
// ---------------------------------------------------------------------------

#define Tn     2048
#define Cn     2048
#define QKVW   3072          // (16 + 2*4) * 128
#define ROWS   4096          // B*T
#define GK     2048          // K dim of both big GEMMs

typedef __half f16;

__device__ __align__(16) float g_qkv[(size_t)ROWS * QKVW];
__device__ __align__(16) f16  g_xh[(size_t)ROWS * GK];
__device__ __align__(16) f16  g_wah[(size_t)QKVW * GK];
__device__ __align__(16) f16  g_wph[(size_t)Cn * GK];
__device__ __align__(16) f16  g_qh[(size_t)2 * 16 * Tn * 128];
__device__ __align__(16) f16  g_kh[(size_t)2 * 4 * Tn * 128];
__device__ __align__(16) f16  g_vth[(size_t)2 * 4 * 128 * Tn];
__device__ __align__(16) f16  g_yh[(size_t)ROWS * Cn];

// 1/sqrt(128) * log2(e): softmax scale + exp->exp2, folded into q
#define QK_SCALE (0.08838834764831845f * 1.4426950408889634f)

// ============================ helpers =======================================
__device__ __forceinline__ float ex2f(float x) {
    float r;
    asm("ex2.approx.ftz.f32 %0, %1;" : "=f"(r) : "f"(x));
    return r;
}
__device__ __forceinline__ uint32_t pkh2(float lo, float hi) {
    __half2 h = __floats2half2_rn(lo, hi);
    return *reinterpret_cast<uint32_t*>(&h);
}
__device__ __forceinline__ void mma_f32a(float (&d)[4], const uint32_t (&a)[4],
                                         const uint32_t* b) {
    asm volatile(
        "mma.sync.aligned.m16n8k16.row.col.f32.f16.f16.f32 "
        "{%0,%1,%2,%3}, {%4,%5,%6,%7}, {%8,%9}, {%0,%1,%2,%3};"
        : "+f"(d[0]), "+f"(d[1]), "+f"(d[2]), "+f"(d[3])
        : "r"(a[0]), "r"(a[1]), "r"(a[2]), "r"(a[3]), "r"(b[0]), "r"(b[1]));
}
__device__ __forceinline__ void ldsm4(uint32_t* r, uint32_t a) {
    asm volatile("ldmatrix.sync.aligned.m8n8.x4.shared.b16 {%0,%1,%2,%3}, [%4];"
                 : "=r"(r[0]), "=r"(r[1]), "=r"(r[2]), "=r"(r[3]) : "r"(a));
}
__device__ __forceinline__ uint32_t smem_u32(const void* p) {
    uint32_t a;
    asm("{ .reg .u64 t; cvta.to.shared.u64 t, %1; cvt.u32.u64 %0, t; }"
        : "=r"(a) : "l"(p));
    return a;
}
#define CP16(dst, src) \
    asm volatile("cp.async.cg.shared.global [%0], [%1], 16;" \
                 :: "r"(dst), "l"(src) : "memory")
#define CPCOMMIT() asm volatile("cp.async.commit_group;" ::: "memory")
#define CPWAIT1()  asm volatile("cp.async.wait_group 1;" ::: "memory")
#define CPWAIT0()  asm volatile("cp.async.wait_group 0;" ::: "memory")

// ---------------------------------------------------------------------------
// convert x -> fp16
// ---------------------------------------------------------------------------
__global__ __launch_bounds__(256) void splitx_kernel(const float* __restrict__ x) {
    size_t i = ((size_t)blockIdx.x * 256 + threadIdx.x) * 4;
    float4 v = *(const float4*)(x + i);
    uint32_t p0 = pkh2(v.x, v.y), p1 = pkh2(v.z, v.w);
    *(uint2*)(g_xh + i) = make_uint2(p0, p1);
}

// ---------------------------------------------------------------------------
// transpose weights to fp16: in [2048][Ccols] fp32 -> [Ccols][2048]
// ---------------------------------------------------------------------------
__global__ __launch_bounds__(256) void wsplit_kernel(
    const float* __restrict__ in, f16* __restrict__ hi, int Ccols)
{
    __shared__ float tb[32][33];
    const int bx = blockIdx.x * 32, by = blockIdx.y * 32;
    const int tx = threadIdx.x, ty = threadIdx.y;
#pragma unroll
    for (int j = 0; j < 32; j += 8)
        tb[ty + j][tx] = in[(size_t)(by + ty + j) * Ccols + bx + tx];
    __syncthreads();
#pragma unroll
    for (int j = 0; j < 32; j += 8) {
        float v = tb[tx][ty + j];
        hi[(size_t)(bx + ty + j) * GK + by + tx] = __float2half_rn(v);
    }
}

// ---------------------------------------------------------------------------
// fp16 1-term GEMM: C[M,N] = A @ B^T, f32 accumulate.
// CTA tile 64x128, kchunk 32, cp.async 3-stage ring, 8 warps (2m x 4n),
// warp tile 32x32. smem stage: A@0 (64 x 80B = 5120), B@5120 (128 x 80B).
// One __syncthreads per ktile; wait_group 1 keeps 2 loads in flight.
// ---------------------------------------------------------------------------
#define GS_STAGE 15360
#define GSM (3 * GS_STAGE)

__global__ __launch_bounds__(256, 3) void hgemm1_kernel(
    const f16* __restrict__ A, const f16* __restrict__ B,
    float* __restrict__ C, int N)
{
    extern __shared__ char sm[];
    const uint32_t sb = smem_u32(sm);
    const int tid = threadIdx.x;
    const int lane = tid & 31, wid = tid >> 5;
    const int lg = lane >> 2, tq = lane & 3;
    const int mi = wid & 1, ni = wid >> 1;
    const size_t m0 = (size_t)blockIdx.y * 64, n0 = (size_t)blockIdx.x * 128;

    const uint32_t abase =
        (uint32_t)((mi * 32 + (lane & 15)) * 80 + (lane >> 4) * 16);
    const uint32_t bbase =
        (uint32_t)(5120 + (ni * 32 + (lane & 7) + ((lane >> 4) * 8)) * 80 +
                   ((lane >> 3) & 1) * 16);

    const int ar = tid >> 2;
    const int ac = tid & 3;
    const f16* pA = A + (m0 + ar) * GK + ac * 8;
    const f16* pB = B + (n0 + ar) * GK + ac * 8;
    const uint32_t sdA = sb + ar * 80 + ac * 16;
    const uint32_t sdB = sb + 5120 + ar * 80 + ac * 16;

    float c[2][4][4];
#pragma unroll
    for (int a = 0; a < 2; a++)
#pragma unroll
        for (int b = 0; b < 4; b++)
#pragma unroll
            for (int d = 0; d < 4; d++) c[a][b][d] = 0.f;

    const int NT = GK / 32;   // 64 ktiles

    // prologue: stages 0 and 1 in flight
#pragma unroll
    for (int p = 0; p < 2; p++) {
        uint32_t dA = sdA + p * GS_STAGE;
        uint32_t dB = sdB + p * GS_STAGE;
        size_t off = (size_t)p * 32;
        CP16(dA,           pA + off);
        CP16(dB,           pB + off);
        CP16(dB + 64 * 80, pB + off + (size_t)64 * GK);
        CPCOMMIT();
    }

    int s = 0;        // stage of ktile kt
    int s2 = 2;       // stage for ktile kt+2
#pragma unroll 1
    for (int kt = 0; kt < NT; kt++) {
        if (kt == NT - 1) { CPWAIT0(); } else { CPWAIT1(); }
        __syncthreads();   // stage kt visible to all; all done reading buffer s2

        if (kt + 2 < NT) {
            uint32_t dA = sdA + s2 * GS_STAGE;
            uint32_t dB = sdB + s2 * GS_STAGE;
            size_t off = (size_t)(kt + 2) * 32;
            CP16(dA,           pA + off);
            CP16(dB,           pB + off);
            CP16(dB + 64 * 80, pB + off + (size_t)64 * GK);
            CPCOMMIT();
        }

        const uint32_t stg = sb + s * GS_STAGE;
#pragma unroll
        for (int kk = 0; kk < 2; kk++) {
            uint32_t ah[2][4];
#pragma unroll
            for (int mt = 0; mt < 2; mt++)
                ldsm4(ah[mt], stg + abase + mt * (16 * 80) + kk * 32);
            uint32_t bb[4][2];
#pragma unroll
            for (int p = 0; p < 2; p++)
                ldsm4(&bb[2 * p][0], stg + bbase + p * (16 * 80) + kk * 32);
#pragma unroll
            for (int mt = 0; mt < 2; mt++)
#pragma unroll
                for (int nt = 0; nt < 4; nt++) mma_f32a(c[mt][nt], ah[mt], bb[nt]);
        }

        s = (s == 2) ? 0 : s + 1;
        s2 = (s2 == 2) ? 0 : s2 + 1;
    }

#pragma unroll
    for (int mt = 0; mt < 2; mt++) {
        size_t r0 = m0 + mi * 32 + mt * 16 + lg;
#pragma unroll
        for (int nt = 0; nt < 4; nt++) {
            size_t col = n0 + ni * 32 + nt * 8 + tq * 2;
            *(float2*)(C + r0 * N + col) = make_float2(c[mt][nt][0], c[mt][nt][1]);
            *(float2*)(C + (r0 + 8) * N + col) = make_float2(c[mt][nt][2], c[mt][nt][3]);
        }
    }
}

// ---------------------------------------------------------------------------
// RoPE + fp16: q (slots 0-3, scaled) -> g_qh; k (slot 4) -> g_kh
// ---------------------------------------------------------------------------
__global__ __launch_bounds__(256) void rope_split_kernel(
    const float* __restrict__ cosb, const float* __restrict__ sinb)
{
    int idx = blockIdx.x * 256 + threadIdx.x;     // ROWS*4*5*64
    int d = idx & 63;
    int rg = idx >> 6;
    int slot = rg % 5;
    int q5 = rg / 5;
    int grp = q5 & 3;
    int row = q5 >> 2;
    int b = row >> 11, t = row & (Tn - 1);

    const float* p = g_qkv + (size_t)row * QKVW + grp * 768 + slot * 128 + d;
    float x1 = p[0], x2 = p[64];
    float cc = cosb[t * 64 + d], ss = sinb[t * 64 + d];
    float o1 = x1 * cc - x2 * ss;
    float o2 = x1 * ss + x2 * cc;

    if (slot < 4) {
        o1 *= QK_SCALE; o2 *= QK_SCALE;
        int head = grp * 4 + slot;
        size_t base = ((size_t)(b * 16 + head) * Tn + t) * 128 + d;
        g_qh[base]      = __float2half_rn(o1);
        g_qh[base + 64] = __float2half_rn(o2);
    } else {
        size_t base = ((size_t)(b * 4 + grp) * Tn + t) * 128 + d;
        g_kh[base]      = __float2half_rn(o1);
        g_kh[base + 64] = __float2half_rn(o2);
    }
}

// ---------------------------------------------------------------------------
// v: transpose -> g_vth [b][g][d][t]
// ---------------------------------------------------------------------------
__global__ __launch_bounds__(256) void vsplit_kernel() {
    __shared__ float tb[32][33];
    const int bg = blockIdx.z;
    const int t0 = blockIdx.x * 32, d0 = blockIdx.y * 32;
    const int tx = threadIdx.x, ty = threadIdx.y;
    const int b = bg >> 2, grp = bg & 3;
#pragma unroll
    for (int j = 0; j < 32; j += 8)
        tb[ty + j][tx] = g_qkv[((size_t)b * Tn + t0 + ty + j) * QKVW +
                               grp * 768 + 640 + d0 + tx];
    __syncthreads();
#pragma unroll
    for (int j = 0; j < 32; j += 8) {
        float v = tb[tx][ty + j];
        size_t o = ((size_t)bg * 128 + d0 + ty + j) * Tn + t0 + tx;
        g_vth[o] = __float2half_rn(v);
    }
}

// ---------------------------------------------------------------------------
// Flash attention, plain fp16 inputs, f32 accumulate.
// CTA = (qb, h, b): 128 q rows, 8 warps x m16. Key tiles of 64.
// smem: Qh [128 x 272B], Kh [64 x 272B], Vth [128 d x 144B] = 70656 B.
// ---------------------------------------------------------------------------
#define AQ_H 0
#define AK_H 34816
#define AV_H 52224
#define ATT_SMEM 70656

__global__ __launch_bounds__(256, 1) void attn_kernel() {
    extern __shared__ char sm[];
    const uint32_t sb = smem_u32(sm);
    const int tid = threadIdx.x;
    const int lane = tid & 31, wid = tid >> 5;
    const int lg = lane >> 2, tq = lane & 3;
    const int qb = blockIdx.x, h = blockIdx.y, b = blockIdx.z;
    const int grp = h >> 2;

    const uint32_t qbase = sb + AQ_H + (wid * 16 + (lane & 15)) * 272 +
                           (lane >> 4) * 16;
    const uint32_t kbase = sb + AK_H + ((lane & 7) + ((lane >> 4) * 8)) * 272 +
                           ((lane >> 3) & 1) * 16;
    const uint32_t vbase = sb + AV_H + ((lane & 7) + ((lane >> 4) * 8)) * 144 +
                           ((lane >> 3) & 1) * 16;

    // load Q, 128 x 128 f16
    {
        const f16* qhp = g_qh + ((size_t)(b * 16 + h) * Tn + qb * 128) * 128;
#pragma unroll
        for (int it = 0; it < 8; it++) {
            int idx = it * 256 + tid;
            int r = idx >> 4, hx = idx & 15;
            *(uint4*)(sm + AQ_H + r * 272 + hx * 16) =
                *(const uint4*)(qhp + (size_t)r * 128 + hx * 8);
        }
    }

    float o[16][4];
#pragma unroll
    for (int i = 0; i < 16; i++)
#pragma unroll
        for (int j = 0; j < 4; j++) o[i][j] = 0.f;
    float m0 = __int_as_float(0xff800000), m1 = m0;
    float l0 = 0.f, l1 = 0.f;

    const f16* khp = g_kh + (size_t)(b * 4 + grp) * Tn * 128;
    const f16* vhp = g_vth + (size_t)(b * 4 + grp) * 128 * Tn;

#pragma unroll 1
    for (int kt = 0; kt < Tn / 64; kt++) {
        __syncthreads();
#pragma unroll
        for (int it = 0; it < 4; it++) {
            int idx = it * 256 + tid;
            int r = idx >> 4, hx = idx & 15;
            size_t go = ((size_t)kt * 64 + r) * 128 + hx * 8;
            *(uint4*)(sm + AK_H + r * 272 + hx * 16) = *(const uint4*)(khp + go);
        }
#pragma unroll
        for (int it = 0; it < 4; it++) {
            int idx = it * 256 + tid;
            int r = idx >> 3, hx = idx & 7;
            size_t go = (size_t)r * Tn + kt * 64 + hx * 8;
            *(uint4*)(sm + AV_H + r * 144 + hx * 16) = *(const uint4*)(vhp + go);
        }
        __syncthreads();

        // ---- S = Q Kh^T, f32 acc ----
        float s[8][4];
#pragma unroll
        for (int i = 0; i < 8; i++)
#pragma unroll
            for (int j = 0; j < 4; j++) s[i][j] = 0.f;

#pragma unroll
        for (int kk = 0; kk < 8; kk++) {
            uint32_t qah[4];
            ldsm4(qah, qbase + kk * 32);
            uint32_t kb[8][2];
#pragma unroll
            for (int p = 0; p < 4; p++)
                ldsm4(&kb[2 * p][0], kbase + p * (16 * 272) + kk * 32);
#pragma unroll
            for (int nt = 0; nt < 8; nt++) mma_f32a(s[nt], qah, kb[nt]);
        }

        // ---- online softmax (2 rows per lane: lg, lg+8) ----
        float mx0 = s[0][0], mx1 = s[0][2];
#pragma unroll
        for (int nt = 0; nt < 8; nt++) {
            mx0 = fmaxf(mx0, fmaxf(s[nt][0], s[nt][1]));
            mx1 = fmaxf(mx1, fmaxf(s[nt][2], s[nt][3]));
        }
        mx0 = fmaxf(mx0, __shfl_xor_sync(0xffffffffu, mx0, 1));
        mx0 = fmaxf(mx0, __shfl_xor_sync(0xffffffffu, mx0, 2));
        mx1 = fmaxf(mx1, __shfl_xor_sync(0xffffffffu, mx1, 1));
        mx1 = fmaxf(mx1, __shfl_xor_sync(0xffffffffu, mx1, 2));
        float mn0 = fmaxf(m0, mx0), mn1 = fmaxf(m1, mx1);
        float cr0 = ex2f(m0 - mn0), cr1 = ex2f(m1 - mn1);
        m0 = mn0; m1 = mn1;
        float sum0 = 0.f, sum1 = 0.f;
#pragma unroll
        for (int nt = 0; nt < 8; nt++) {
            s[nt][0] = ex2f(s[nt][0] - mn0);
            s[nt][1] = ex2f(s[nt][1] - mn0);
            s[nt][2] = ex2f(s[nt][2] - mn1);
            s[nt][3] = ex2f(s[nt][3] - mn1);
            sum0 += s[nt][0] + s[nt][1];
            sum1 += s[nt][2] + s[nt][3];
        }
        sum0 += __shfl_xor_sync(0xffffffffu, sum0, 1);
        sum0 += __shfl_xor_sync(0xffffffffu, sum0, 2);
        sum1 += __shfl_xor_sync(0xffffffffu, sum1, 1);
        sum1 += __shfl_xor_sync(0xffffffffu, sum1, 2);
        l0 = l0 * cr0 + sum0;
        l1 = l1 * cr1 + sum1;
#pragma unroll
        for (int nt = 0; nt < 16; nt++) {
            o[nt][0] *= cr0; o[nt][1] *= cr0;
            o[nt][2] *= cr1; o[nt][3] *= cr1;
        }

        // ---- O += Ph Vh, f32 acc ----
#pragma unroll
        for (int kk = 0; kk < 4; kk++) {
            uint32_t ph[4];
#pragma unroll
            for (int q2 = 0; q2 < 2; q2++) {
                ph[2 * q2]     = pkh2(s[2 * kk + q2][0], s[2 * kk + q2][1]);
                ph[2 * q2 + 1] = pkh2(s[2 * kk + q2][2], s[2 * kk + q2][3]);
            }
#pragma unroll
            for (int blk = 0; blk < 2; blk++) {
                uint32_t vb[8][2];
#pragma unroll
                for (int p = 0; p < 4; p++)
                    ldsm4(&vb[2 * p][0], vbase + (blk * 64 + p * 16) * 144 + kk * 32);
#pragma unroll
                for (int j = 0; j < 8; j++) mma_f32a(o[blk * 8 + j], ph, vb[j]);
            }
        }
    }

    // ---- epilogue: y = O / l -> fp16 ----
    float i0 = 1.f / l0, i1 = 1.f / l1;
    size_t row0 = (size_t)b * Tn + qb * 128 + wid * 16 + lg;
#pragma unroll
    for (int nt = 0; nt < 16; nt++) {
        int col = h * 128 + nt * 8 + tq * 2;
        *(uint32_t*)(g_yh + row0 * Cn + col) =
            pkh2(o[nt][0] * i0, o[nt][1] * i0);
        *(uint32_t*)(g_yh + (row0 + 8) * Cn + col) =
            pkh2(o[nt][2] * i1, o[nt][3] * i1);
    }
}

// ---------------------------------------------------------------------------
extern "C" void kernel_launch(void* const* d_in, const int* in_sizes, int n_in,
                              void* d_out, int out_size) {
    const float* x      = (const float*)d_in[0];
    const float* cosb   = (const float*)d_in[1];
    const float* sinb   = (const float*)d_in[2];
    const float* w_attn = (const float*)d_in[3];
    const float* w_proj = (const float*)d_in[4];
    float* out = (float*)d_out;
    (void)in_sizes; (void)n_in; (void)out_size;

    (void)cudaFuncSetAttribute(hgemm1_kernel,
                               cudaFuncAttributeMaxDynamicSharedMemorySize, GSM);
    (void)cudaFuncSetAttribute(attn_kernel,
                               cudaFuncAttributeMaxDynamicSharedMemorySize, ATT_SMEM);

    float* qkvp = nullptr;
    f16 *xh, *wah, *wph, *yh;
    (void)cudaGetSymbolAddress((void**)&qkvp, g_qkv);
    (void)cudaGetSymbolAddress((void**)&xh, g_xh);
    (void)cudaGetSymbolAddress((void**)&wah, g_wah);
    (void)cudaGetSymbolAddress((void**)&wph, g_wph);
    (void)cudaGetSymbolAddress((void**)&yh, g_yh);

    // 0. fp16 conversions
    splitx_kernel<<<(ROWS * GK / 4) / 256, 256>>>(x);
    wsplit_kernel<<<dim3(QKVW / 32, GK / 32), dim3(32, 8)>>>(w_attn, wah, QKVW);
    wsplit_kernel<<<dim3(Cn / 32, GK / 32), dim3(32, 8)>>>(w_proj, wph, Cn);
    // 1. qkv = x @ w_attn (fp16, 64x128 tiles, 3-stage)
    hgemm1_kernel<<<dim3(QKVW / 128, ROWS / 64), 256, GSM>>>(xh, wah, qkvp, QKVW);
    // 2. RoPE -> q, k (fp16)
    rope_split_kernel<<<(ROWS * 4 * 5 * 64) / 256, 256>>>(cosb, sinb);
    // 3. v transpose (fp16)
    vsplit_kernel<<<dim3(Tn / 32, 4, 8), dim3(32, 8)>>>();
    // 4. attention -> yh
    attn_kernel<<<dim3(Tn / 128, 16, 2), 256, ATT_SMEM>>>();
    // 5. out = y @ w_proj (fp16, 64x128 tiles, 3-stage)
    hgemm1_kernel<<<dim3(Cn / 128, ROWS / 64), 256, GSM>>>(yh, wph, out, Cn);
}

// round 15
// speedup vs baseline: 1.2373x; 1.0270x over previous
#include <cuda_runtime.h>
#include <cuda_fp16.h>
#include <cstdint>
#include <cstddef>

// ---------------------------------------------------------------------------
// SelfAttention on sm_103, mma.sync fp16, fp32 accumulate everywhere.
// R15: RoPE + V-transpose fused into gemm1's epilogue. Each gemm1 CTA tile
// (64 rows x 128 cols) is exactly one (group, slot): q/k slots get RoPE in
// fp32 (cos/sin from global) -> fp16 g_qh/g_kh; the v slot is transposed via
// smem -> g_vth. Eliminates g_qkv (50MB fp32), the rope & vsplit kernels
// (~75MB traffic) and 2 launches. Math bit-identical to R14 (same fp32
// values, same rounding points): rel_err must stay 7.065852e-4.
// GEMM mainloop = R14 (64x128 tile, 3-stage ring, 3 CTAs/SM).
// ---------------------------------------------------------------------------

#define Tn     2048
#define Cn     2048
#define QKVW   3072          // (16 + 2*4) * 128
#define ROWS   4096          // B*T
#define GK     2048          // K dim of both big GEMMs

typedef __half f16;

__device__ __align__(16) f16  g_xh[(size_t)ROWS * GK];
__device__ __align__(16) f16  g_wah[(size_t)QKVW * GK];
__device__ __align__(16) f16  g_wph[(size_t)Cn * GK];
__device__ __align__(16) f16  g_qh[(size_t)2 * 16 * Tn * 128];
__device__ __align__(16) f16  g_kh[(size_t)2 * 4 * Tn * 128];
__device__ __align__(16) f16  g_vth[(size_t)2 * 4 * 128 * Tn];
__device__ __align__(16) f16  g_yh[(size_t)ROWS * Cn];

// 1/sqrt(128) * log2(e): softmax scale + exp->exp2, folded into q
#define QK_SCALE (0.08838834764831845f * 1.4426950408889634f)

// ============================ helpers =======================================
__device__ __forceinline__ float ex2f(float x) {
    float r;
    asm("ex2.approx.ftz.f32 %0, %1;" : "=f"(r) : "f"(x));
    return r;
}
__device__ __forceinline__ uint32_t pkh2(float lo, float hi) {
    __half2 h = __floats2half2_rn(lo, hi);
    return *reinterpret_cast<uint32_t*>(&h);
}
__device__ __forceinline__ void mma_f32a(float (&d)[4], const uint32_t (&a)[4],
                                         const uint32_t* b) {
    asm volatile(
        "mma.sync.aligned.m16n8k16.row.col.f32.f16.f16.f32 "
        "{%0,%1,%2,%3}, {%4,%5,%6,%7}, {%8,%9}, {%0,%1,%2,%3};"
        : "+f"(d[0]), "+f"(d[1]), "+f"(d[2]), "+f"(d[3])
        : "r"(a[0]), "r"(a[1]), "r"(a[2]), "r"(a[3]), "r"(b[0]), "r"(b[1]));
}
__device__ __forceinline__ void ldsm4(uint32_t* r, uint32_t a) {
    asm volatile("ldmatrix.sync.aligned.m8n8.x4.shared.b16 {%0,%1,%2,%3}, [%4];"
                 : "=r"(r[0]), "=r"(r[1]), "=r"(r[2]), "=r"(r[3]) : "r"(a));
}
__device__ __forceinline__ uint32_t smem_u32(const void* p) {
    uint32_t a;
    asm("{ .reg .u64 t; cvta.to.shared.u64 t, %1; cvt.u32.u64 %0, t; }"
        : "=r"(a) : "l"(p));
    return a;
}
#define CP16(dst, src) \
    asm volatile("cp.async.cg.shared.global [%0], [%1], 16;" \
                 :: "r"(dst), "l"(src) : "memory")
#define CPCOMMIT() asm volatile("cp.async.commit_group;" ::: "memory")
#define CPWAIT1()  asm volatile("cp.async.wait_group 1;" ::: "memory")
#define CPWAIT0()  asm volatile("cp.async.wait_group 0;" ::: "memory")

// ---------------------------------------------------------------------------
// convert x -> fp16
// ---------------------------------------------------------------------------
__global__ __launch_bounds__(256) void splitx_kernel(const float* __restrict__ x) {
    size_t i = ((size_t)blockIdx.x * 256 + threadIdx.x) * 4;
    float4 v = *(const float4*)(x + i);
    uint32_t p0 = pkh2(v.x, v.y), p1 = pkh2(v.z, v.w);
    *(uint2*)(g_xh + i) = make_uint2(p0, p1);
}

// ---------------------------------------------------------------------------
// transpose weights to fp16: in [2048][Ccols] fp32 -> [Ccols][2048]
// ---------------------------------------------------------------------------
__global__ __launch_bounds__(256) void wsplit_kernel(
    const float* __restrict__ in, f16* __restrict__ hi, int Ccols)
{
    __shared__ float tb[32][33];
    const int bx = blockIdx.x * 32, by = blockIdx.y * 32;
    const int tx = threadIdx.x, ty = threadIdx.y;
#pragma unroll
    for (int j = 0; j < 32; j += 8)
        tb[ty + j][tx] = in[(size_t)(by + ty + j) * Ccols + bx + tx];
    __syncthreads();
#pragma unroll
    for (int j = 0; j < 32; j += 8) {
        float v = tb[tx][ty + j];
        hi[(size_t)(bx + ty + j) * GK + by + tx] = __float2half_rn(v);
    }
}

// ============================================================================
// GEMM mainloop body (R14): 64x128 tile, kchunk 32, 3-stage cp.async ring.
// Produces c[2][4][4] per thread. Shared by both GEMM kernels via macro-free
// inline function (acc passed by reference).
// ============================================================================
#define GS_STAGE 15360
#define GSM (3 * GS_STAGE)

__device__ __forceinline__ void gemm_mainloop(
    const f16* __restrict__ A, const f16* __restrict__ B,
    char* sm, uint32_t sb, size_t m0, size_t n0, float (&c)[2][4][4])
{
    const int tid = threadIdx.x;
    const int lane = tid & 31, wid = tid >> 5;
    const int mi = wid & 1, ni = wid >> 1;

    const uint32_t abase =
        (uint32_t)((mi * 32 + (lane & 15)) * 80 + (lane >> 4) * 16);
    const uint32_t bbase =
        (uint32_t)(5120 + (ni * 32 + (lane & 7) + ((lane >> 4) * 8)) * 80 +
                   ((lane >> 3) & 1) * 16);

    const int ar = tid >> 2;
    const int ac = tid & 3;
    const f16* pA = A + (m0 + ar) * GK + ac * 8;
    const f16* pB = B + (n0 + ar) * GK + ac * 8;
    const uint32_t sdA = sb + ar * 80 + ac * 16;
    const uint32_t sdB = sb + 5120 + ar * 80 + ac * 16;

#pragma unroll
    for (int a = 0; a < 2; a++)
#pragma unroll
        for (int b = 0; b < 4; b++)
#pragma unroll
            for (int d = 0; d < 4; d++) c[a][b][d] = 0.f;

    const int NT = GK / 32;

#pragma unroll
    for (int p = 0; p < 2; p++) {
        uint32_t dA = sdA + p * GS_STAGE;
        uint32_t dB = sdB + p * GS_STAGE;
        size_t off = (size_t)p * 32;
        CP16(dA,           pA + off);
        CP16(dB,           pB + off);
        CP16(dB + 64 * 80, pB + off + (size_t)64 * GK);
        CPCOMMIT();
    }

    int s = 0, s2 = 2;
#pragma unroll 1
    for (int kt = 0; kt < NT; kt++) {
        if (kt == NT - 1) { CPWAIT0(); } else { CPWAIT1(); }
        __syncthreads();

        if (kt + 2 < NT) {
            uint32_t dA = sdA + s2 * GS_STAGE;
            uint32_t dB = sdB + s2 * GS_STAGE;
            size_t off = (size_t)(kt + 2) * 32;
            CP16(dA,           pA + off);
            CP16(dB,           pB + off);
            CP16(dB + 64 * 80, pB + off + (size_t)64 * GK);
            CPCOMMIT();
        }

        const uint32_t stg = sb + s * GS_STAGE;
#pragma unroll
        for (int kk = 0; kk < 2; kk++) {
            uint32_t ah[2][4];
#pragma unroll
            for (int mt = 0; mt < 2; mt++)
                ldsm4(ah[mt], stg + abase + mt * (16 * 80) + kk * 32);
            uint32_t bb[4][2];
#pragma unroll
            for (int p = 0; p < 2; p++)
                ldsm4(&bb[2 * p][0], stg + bbase + p * (16 * 80) + kk * 32);
#pragma unroll
            for (int mt = 0; mt < 2; mt++)
#pragma unroll
                for (int nt = 0; nt < 4; nt++) mma_f32a(c[mt][nt], ah[mt], bb[nt]);
        }

        s = (s == 2) ? 0 : s + 1;
        s2 = (s2 == 2) ? 0 : s2 + 1;
    }
}

// ---------------------------------------------------------------------------
// gemm2: plain fp32-output GEMM (y @ w_proj -> out)
// ---------------------------------------------------------------------------
__global__ __launch_bounds__(256, 3) void hgemm1_kernel(
    const f16* __restrict__ A, const f16* __restrict__ B,
    float* __restrict__ C, int N)
{
    extern __shared__ char sm[];
    const uint32_t sb = smem_u32(sm);
    const int tid = threadIdx.x;
    const int lane = tid & 31, wid = tid >> 5;
    const int lg = lane >> 2, tq = lane & 3;
    const int mi = wid & 1, ni = wid >> 1;
    const size_t m0 = (size_t)blockIdx.y * 64, n0 = (size_t)blockIdx.x * 128;

    float c[2][4][4];
    gemm_mainloop(A, B, sm, sb, m0, n0, c);

#pragma unroll
    for (int mt = 0; mt < 2; mt++) {
        size_t r0 = m0 + mi * 32 + mt * 16 + lg;
#pragma unroll
        for (int nt = 0; nt < 4; nt++) {
            size_t col = n0 + ni * 32 + nt * 8 + tq * 2;
            *(float2*)(C + r0 * N + col) = make_float2(c[mt][nt][0], c[mt][nt][1]);
            *(float2*)(C + (r0 + 8) * N + col) = make_float2(c[mt][nt][2], c[mt][nt][3]);
        }
    }
}

// ---------------------------------------------------------------------------
// gemm1 fused: x @ w_attn with RoPE/V-transpose epilogue.
// blockIdx.x in 0..23: grp = bx/6, slot = bx%6 (q0..q3, k, v).
// Epilogue stages accumulators in smem [64][132] f32 (33.8KB <= 45KB ring).
// ---------------------------------------------------------------------------
__global__ __launch_bounds__(256, 3) void hgemm_qkv_kernel(
    const f16* __restrict__ A, const f16* __restrict__ B,
    const float* __restrict__ cosb, const float* __restrict__ sinb)
{
    extern __shared__ char sm[];
    const uint32_t sb = smem_u32(sm);
    const int tid = threadIdx.x;
    const int lane = tid & 31, wid = tid >> 5;
    const int lg = lane >> 2, tq = lane & 3;
    const int mi = wid & 1, ni = wid >> 1;
    const size_t m0 = (size_t)blockIdx.y * 64, n0 = (size_t)blockIdx.x * 128;

    float c[2][4][4];
    gemm_mainloop(A, B, sm, sb, m0, n0, c);

    // ---- fused epilogue ----
    __syncthreads();                       // mainloop reads done; reuse smem
    float* se = (float*)sm;                // [64][132]
#pragma unroll
    for (int mt = 0; mt < 2; mt++) {
        int row = mi * 32 + mt * 16 + lg;
#pragma unroll
        for (int nt = 0; nt < 4; nt++) {
            int col = ni * 32 + nt * 8 + tq * 2;
            se[row * 132 + col]           = c[mt][nt][0];
            se[row * 132 + col + 1]       = c[mt][nt][1];
            se[(row + 8) * 132 + col]     = c[mt][nt][2];
            se[(row + 8) * 132 + col + 1] = c[mt][nt][3];
        }
    }
    __syncthreads();

    const int grp = blockIdx.x / 6, slot = blockIdx.x % 6;
    const int b = (int)(m0 >> 11);          // 64-row tile never crosses batch
    const int tbase = (int)(m0 & (Tn - 1));

    if (slot < 5) {
        // RoPE path (q: scaled; k: unscaled), 64 rows x 64 d-pairs
        const float scale = (slot < 4) ? (float)QK_SCALE : 1.0f;
        f16* dst;
        size_t hb;
        if (slot < 4) { dst = g_qh; hb = (size_t)(b * 16 + grp * 4 + slot) * Tn; }
        else          { dst = g_kh; hb = (size_t)(b * 4 + grp) * Tn; }
#pragma unroll
        for (int it = 0; it < 16; it++) {
            int idx = it * 256 + tid;       // 0..4095
            int d = idx & 63;
            int row = idx >> 6;             // 0..63
            int t = tbase + row;
            float x1 = se[row * 132 + d];
            float x2 = se[row * 132 + d + 64];
            float cc = cosb[t * 64 + d], ss = sinb[t * 64 + d];
            float o1 = (x1 * cc - x2 * ss) * scale;
            float o2 = (x1 * ss + x2 * cc) * scale;
            size_t base = (hb + t) * 128 + d;
            dst[base]      = __float2half_rn(o1);
            dst[base + 64] = __float2half_rn(o2);
        }
    } else {
        // V path: transpose to g_vth[(b*4+grp)*128 + d][t]
        const size_t vb = (size_t)(b * 4 + grp) * 128;
#pragma unroll
        for (int it = 0; it < 8; it++) {
            int idx = it * 256 + tid;       // 0..2047
            int d = idx >> 4;               // 0..127
            int tc = (idx & 15) * 4;        // 0..60
            uint32_t lo = pkh2(se[(tc + 0) * 132 + d], se[(tc + 1) * 132 + d]);
            uint32_t hi = pkh2(se[(tc + 2) * 132 + d], se[(tc + 3) * 132 + d]);
            *(uint2*)(g_vth + (vb + d) * Tn + tbase + tc) = make_uint2(lo, hi);
        }
    }
}

// ---------------------------------------------------------------------------
// Flash attention, plain fp16 inputs, f32 accumulate (R11/R14, unchanged).
// ---------------------------------------------------------------------------
#define AQ_H 0
#define AK_H 34816
#define AV_H 52224
#define ATT_SMEM 70656

__global__ __launch_bounds__(256, 1) void attn_kernel() {
    extern __shared__ char sm[];
    const uint32_t sb = smem_u32(sm);
    const int tid = threadIdx.x;
    const int lane = tid & 31, wid = tid >> 5;
    const int lg = lane >> 2, tq = lane & 3;
    const int qb = blockIdx.x, h = blockIdx.y, b = blockIdx.z;
    const int grp = h >> 2;

    const uint32_t qbase = sb + AQ_H + (wid * 16 + (lane & 15)) * 272 +
                           (lane >> 4) * 16;
    const uint32_t kbase = sb + AK_H + ((lane & 7) + ((lane >> 4) * 8)) * 272 +
                           ((lane >> 3) & 1) * 16;
    const uint32_t vbase = sb + AV_H + ((lane & 7) + ((lane >> 4) * 8)) * 144 +
                           ((lane >> 3) & 1) * 16;

    {
        const f16* qhp = g_qh + ((size_t)(b * 16 + h) * Tn + qb * 128) * 128;
#pragma unroll
        for (int it = 0; it < 8; it++) {
            int idx = it * 256 + tid;
            int r = idx >> 4, hx = idx & 15;
            *(uint4*)(sm + AQ_H + r * 272 + hx * 16) =
                *(const uint4*)(qhp + (size_t)r * 128 + hx * 8);
        }
    }

    float o[16][4];
#pragma unroll
    for (int i = 0; i < 16; i++)
#pragma unroll
        for (int j = 0; j < 4; j++) o[i][j] = 0.f;
    float m0 = __int_as_float(0xff800000), m1 = m0;
    float l0 = 0.f, l1 = 0.f;

    const f16* khp = g_kh + (size_t)(b * 4 + grp) * Tn * 128;
    const f16* vhp = g_vth + (size_t)(b * 4 + grp) * 128 * Tn;

#pragma unroll 1
    for (int kt = 0; kt < Tn / 64; kt++) {
        __syncthreads();
#pragma unroll
        for (int it = 0; it < 4; it++) {
            int idx = it * 256 + tid;
            int r = idx >> 4, hx = idx & 15;
            size_t go = ((size_t)kt * 64 + r) * 128 + hx * 8;
            *(uint4*)(sm + AK_H + r * 272 + hx * 16) = *(const uint4*)(khp + go);
        }
#pragma unroll
        for (int it = 0; it < 4; it++) {
            int idx = it * 256 + tid;
            int r = idx >> 3, hx = idx & 7;
            size_t go = (size_t)r * Tn + kt * 64 + hx * 8;
            *(uint4*)(sm + AV_H + r * 144 + hx * 16) = *(const uint4*)(vhp + go);
        }
        __syncthreads();

        float s[8][4];
#pragma unroll
        for (int i = 0; i < 8; i++)
#pragma unroll
            for (int j = 0; j < 4; j++) s[i][j] = 0.f;

#pragma unroll
        for (int kk = 0; kk < 8; kk++) {
            uint32_t qah[4];
            ldsm4(qah, qbase + kk * 32);
            uint32_t kb[8][2];
#pragma unroll
            for (int p = 0; p < 4; p++)
                ldsm4(&kb[2 * p][0], kbase + p * (16 * 272) + kk * 32);
#pragma unroll
            for (int nt = 0; nt < 8; nt++) mma_f32a(s[nt], qah, kb[nt]);
        }

        float mx0 = s[0][0], mx1 = s[0][2];
#pragma unroll
        for (int nt = 0; nt < 8; nt++) {
            mx0 = fmaxf(mx0, fmaxf(s[nt][0], s[nt][1]));
            mx1 = fmaxf(mx1, fmaxf(s[nt][2], s[nt][3]));
        }
        mx0 = fmaxf(mx0, __shfl_xor_sync(0xffffffffu, mx0, 1));
        mx0 = fmaxf(mx0, __shfl_xor_sync(0xffffffffu, mx0, 2));
        mx1 = fmaxf(mx1, __shfl_xor_sync(0xffffffffu, mx1, 1));
        mx1 = fmaxf(mx1, __shfl_xor_sync(0xffffffffu, mx1, 2));
        float mn0 = fmaxf(m0, mx0), mn1 = fmaxf(m1, mx1);
        float cr0 = ex2f(m0 - mn0), cr1 = ex2f(m1 - mn1);
        m0 = mn0; m1 = mn1;
        float sum0 = 0.f, sum1 = 0.f;
#pragma unroll
        for (int nt = 0; nt < 8; nt++) {
            s[nt][0] = ex2f(s[nt][0] - mn0);
            s[nt][1] = ex2f(s[nt][1] - mn0);
            s[nt][2] = ex2f(s[nt][2] - mn1);
            s[nt][3] = ex2f(s[nt][3] - mn1);
            sum0 += s[nt][0] + s[nt][1];
            sum1 += s[nt][2] + s[nt][3];
        }
        sum0 += __shfl_xor_sync(0xffffffffu, sum0, 1);
        sum0 += __shfl_xor_sync(0xffffffffu, sum0, 2);
        sum1 += __shfl_xor_sync(0xffffffffu, sum1, 1);
        sum1 += __shfl_xor_sync(0xffffffffu, sum1, 2);
        l0 = l0 * cr0 + sum0;
        l1 = l1 * cr1 + sum1;
#pragma unroll
        for (int nt = 0; nt < 16; nt++) {
            o[nt][0] *= cr0; o[nt][1] *= cr0;
            o[nt][2] *= cr1; o[nt][3] *= cr1;
        }

#pragma unroll
        for (int kk = 0; kk < 4; kk++) {
            uint32_t ph[4];
#pragma unroll
            for (int q2 = 0; q2 < 2; q2++) {
                ph[2 * q2]     = pkh2(s[2 * kk + q2][0], s[2 * kk + q2][1]);
                ph[2 * q2 + 1] = pkh2(s[2 * kk + q2][2], s[2 * kk + q2][3]);
            }
#pragma unroll
            for (int blk = 0; blk < 2; blk++) {
                uint32_t vb[8][2];
#pragma unroll
                for (int p = 0; p < 4; p++)
                    ldsm4(&vb[2 * p][0], vbase + (blk * 64 + p * 16) * 144 + kk * 32);
#pragma unroll
                for (int j = 0; j < 8; j++) mma_f32a(o[blk * 8 + j], ph, vb[j]);
            }
        }
    }

    float i0 = 1.f / l0, i1 = 1.f / l1;
    size_t row0 = (size_t)b * Tn + qb * 128 + wid * 16 + lg;
#pragma unroll
    for (int nt = 0; nt < 16; nt++) {
        int col = h * 128 + nt * 8 + tq * 2;
        *(uint32_t*)(g_yh + row0 * Cn + col) =
            pkh2(o[nt][0] * i0, o[nt][1] * i0);
        *(uint32_t*)(g_yh + (row0 + 8) * Cn + col) =
            pkh2(o[nt][2] * i1, o[nt][3] * i1);
    }
}

// ---------------------------------------------------------------------------
extern "C" void kernel_launch(void* const* d_in, const int* in_sizes, int n_in,
                              void* d_out, int out_size) {
    const float* x      = (const float*)d_in[0];
    const float* cosb   = (const float*)d_in[1];
    const float* sinb   = (const float*)d_in[2];
    const float* w_attn = (const float*)d_in[3];
    const float* w_proj = (const float*)d_in[4];
    float* out = (float*)d_out;
    (void)in_sizes; (void)n_in; (void)out_size;

    (void)cudaFuncSetAttribute(hgemm1_kernel,
                               cudaFuncAttributeMaxDynamicSharedMemorySize, GSM);
    (void)cudaFuncSetAttribute(hgemm_qkv_kernel,
                               cudaFuncAttributeMaxDynamicSharedMemorySize, GSM);
    (void)cudaFuncSetAttribute(attn_kernel,
                               cudaFuncAttributeMaxDynamicSharedMemorySize, ATT_SMEM);

    f16 *xh, *wah, *wph, *yh;
    (void)cudaGetSymbolAddress((void**)&xh, g_xh);
    (void)cudaGetSymbolAddress((void**)&wah, g_wah);
    (void)cudaGetSymbolAddress((void**)&wph, g_wph);
    (void)cudaGetSymbolAddress((void**)&yh, g_yh);

    // 0. fp16 conversions
    splitx_kernel<<<(ROWS * GK / 4) / 256, 256>>>(x);
    wsplit_kernel<<<dim3(QKVW / 32, GK / 32), dim3(32, 8)>>>(w_attn, wah, QKVW);
    wsplit_kernel<<<dim3(Cn / 32, GK / 32), dim3(32, 8)>>>(w_proj, wph, Cn);
    // 1. qkv = x @ w_attn, fused RoPE + v-transpose epilogue
    hgemm_qkv_kernel<<<dim3(QKVW / 128, ROWS / 64), 256, GSM>>>(xh, wah, cosb, sinb);
    // 2. attention -> yh
    attn_kernel<<<dim3(Tn / 128, 16, 2), 256, ATT_SMEM>>>();
    // 3. out = y @ w_proj
    hgemm1_kernel<<<dim3(Cn / 128, ROWS / 64), 256, GSM>>>(yh, wph, out, Cn);
}

// round 16
// speedup vs baseline: 1.2610x; 1.0192x over previous
#include <cuda_runtime.h>
#include <cuda_fp16.h>
#include <cstdint>
#include <cstddef>

// ---------------------------------------------------------------------------
// SelfAttention on sm_103, mma.sync fp16, fp32 accumulate everywhere.
// R16: (1) three prep kernels merged into one launch (partitioned grid) to
// cut launch gaps and overlap their waves; (2) GEMM mainloop reordered:
// kk=0 fragment ldsm BEFORE next-stage cp.async issue, so the 6 volatile
// CP16s overlap MMA issue instead of sitting on the ktile critical path.
// fp32 op sequence unchanged -> rel_err must stay exactly 7.065852e-4.
// ---------------------------------------------------------------------------

#define Tn     2048
#define Cn     2048
#define QKVW   3072          // (16 + 2*4) * 128
#define ROWS   4096          // B*T
#define GK     2048          // K dim of both big GEMMs

typedef __half f16;

__device__ __align__(16) f16  g_xh[(size_t)ROWS * GK];
__device__ __align__(16) f16  g_wah[(size_t)QKVW * GK];
__device__ __align__(16) f16  g_wph[(size_t)Cn * GK];
__device__ __align__(16) f16  g_qh[(size_t)2 * 16 * Tn * 128];
__device__ __align__(16) f16  g_kh[(size_t)2 * 4 * Tn * 128];
__device__ __align__(16) f16  g_vth[(size_t)2 * 4 * 128 * Tn];
__device__ __align__(16) f16  g_yh[(size_t)ROWS * Cn];

// 1/sqrt(128) * log2(e): softmax scale + exp->exp2, folded into q
#define QK_SCALE (0.08838834764831845f * 1.4426950408889634f)

// ============================ helpers =======================================
__device__ __forceinline__ float ex2f(float x) {
    float r;
    asm("ex2.approx.ftz.f32 %0, %1;" : "=f"(r) : "f"(x));
    return r;
}
__device__ __forceinline__ uint32_t pkh2(float lo, float hi) {
    __half2 h = __floats2half2_rn(lo, hi);
    return *reinterpret_cast<uint32_t*>(&h);
}
__device__ __forceinline__ void mma_f32a(float (&d)[4], const uint32_t (&a)[4],
                                         const uint32_t* b) {
    asm volatile(
        "mma.sync.aligned.m16n8k16.row.col.f32.f16.f16.f32 "
        "{%0,%1,%2,%3}, {%4,%5,%6,%7}, {%8,%9}, {%0,%1,%2,%3};"
        : "+f"(d[0]), "+f"(d[1]), "+f"(d[2]), "+f"(d[3])
        : "r"(a[0]), "r"(a[1]), "r"(a[2]), "r"(a[3]), "r"(b[0]), "r"(b[1]));
}
__device__ __forceinline__ void ldsm4(uint32_t* r, uint32_t a) {
    asm volatile("ldmatrix.sync.aligned.m8n8.x4.shared.b16 {%0,%1,%2,%3}, [%4];"
                 : "=r"(r[0]), "=r"(r[1]), "=r"(r[2]), "=r"(r[3]) : "r"(a));
}
__device__ __forceinline__ uint32_t smem_u32(const void* p) {
    uint32_t a;
    asm("{ .reg .u64 t; cvta.to.shared.u64 t, %1; cvt.u32.u64 %0, t; }"
        : "=r"(a) : "l"(p));
    return a;
}
#define CP16(dst, src) \
    asm volatile("cp.async.cg.shared.global [%0], [%1], 16;" \
                 :: "r"(dst), "l"(src) : "memory")
#define CPCOMMIT() asm volatile("cp.async.commit_group;" ::: "memory")
#define CPWAIT1()  asm volatile("cp.async.wait_group 1;" ::: "memory")
#define CPWAIT0()  asm volatile("cp.async.wait_group 0;" ::: "memory")

// ---------------------------------------------------------------------------
// merged prep: [0,8192) x->fp16 ; [8192,14336) w_attn T+cvt ; rest w_proj
// ---------------------------------------------------------------------------
__global__ __launch_bounds__(256) void prep_kernel(
    const float* __restrict__ x,
    const float* __restrict__ wa,
    const float* __restrict__ wp)
{
    __shared__ float tb[32][33];
    const int tid = threadIdx.x;
    const int bx = blockIdx.x;

    if (bx < 8192) {
        size_t i = ((size_t)bx * 256 + tid) * 4;
        float4 v = *(const float4*)(x + i);
        uint32_t p0 = pkh2(v.x, v.y), p1 = pkh2(v.z, v.w);
        *(uint2*)(g_xh + i) = make_uint2(p0, p1);
        return;
    }

    const float* in;
    f16* hi;
    int Ccols, cx, cy;
    if (bx < 8192 + 6144) {
        int t = bx - 8192;
        in = wa; hi = g_wah; Ccols = QKVW;
        cx = t % 96; cy = t / 96;
    } else {
        int t = bx - 14336;
        in = wp; hi = g_wph; Ccols = Cn;
        cx = t % 64; cy = t / 64;
    }
    const int bxo = cx * 32, byo = cy * 32;
    const int tx = tid & 31, ty = tid >> 5;
#pragma unroll
    for (int j = 0; j < 32; j += 8)
        tb[ty + j][tx] = in[(size_t)(byo + ty + j) * Ccols + bxo + tx];
    __syncthreads();
#pragma unroll
    for (int j = 0; j < 32; j += 8) {
        float v = tb[tx][ty + j];
        hi[(size_t)(bxo + ty + j) * GK + byo + tx] = __float2half_rn(v);
    }
}

// ============================================================================
// GEMM mainloop: 64x128 tile, kchunk 32, 3-stage cp.async ring, reordered so
// kk=0 fragments load before the next-stage cp.async issue.
// ============================================================================
#define GS_STAGE 15360
#define GSM (3 * GS_STAGE)

__device__ __forceinline__ void gemm_mainloop(
    const f16* __restrict__ A, const f16* __restrict__ B,
    char* sm, uint32_t sb, size_t m0, size_t n0, float (&c)[2][4][4])
{
    const int tid = threadIdx.x;
    const int lane = tid & 31, wid = tid >> 5;
    const int mi = wid & 1, ni = wid >> 1;

    const uint32_t abase =
        (uint32_t)((mi * 32 + (lane & 15)) * 80 + (lane >> 4) * 16);
    const uint32_t bbase =
        (uint32_t)(5120 + (ni * 32 + (lane & 7) + ((lane >> 4) * 8)) * 80 +
                   ((lane >> 3) & 1) * 16);

    const int ar = tid >> 2;
    const int ac = tid & 3;
    const f16* pA = A + (m0 + ar) * GK + ac * 8;
    const f16* pB = B + (n0 + ar) * GK + ac * 8;
    const uint32_t sdA = sb + ar * 80 + ac * 16;
    const uint32_t sdB = sb + 5120 + ar * 80 + ac * 16;

#pragma unroll
    for (int a = 0; a < 2; a++)
#pragma unroll
        for (int b = 0; b < 4; b++)
#pragma unroll
            for (int d = 0; d < 4; d++) c[a][b][d] = 0.f;

    const int NT = GK / 32;

#pragma unroll
    for (int p = 0; p < 2; p++) {
        uint32_t dA = sdA + p * GS_STAGE;
        uint32_t dB = sdB + p * GS_STAGE;
        size_t off = (size_t)p * 32;
        CP16(dA,           pA + off);
        CP16(dB,           pB + off);
        CP16(dB + 64 * 80, pB + off + (size_t)64 * GK);
        CPCOMMIT();
    }

    int s = 0, s2 = 2;
#pragma unroll 1
    for (int kt = 0; kt < NT; kt++) {
        if (kt == NT - 1) { CPWAIT0(); } else { CPWAIT1(); }
        __syncthreads();

        const uint32_t stg = sb + s * GS_STAGE;

        // fragments for kk=0 first (off critical path of cp.async issue)
        uint32_t ah[2][4], bb[4][2];
#pragma unroll
        for (int mt = 0; mt < 2; mt++)
            ldsm4(ah[mt], stg + abase + mt * (16 * 80));
#pragma unroll
        for (int p = 0; p < 2; p++)
            ldsm4(&bb[2 * p][0], stg + bbase + p * (16 * 80));

        // prefetch stage kt+2 (overlaps with kk=0 MMAs below)
        if (kt + 2 < NT) {
            uint32_t dA = sdA + s2 * GS_STAGE;
            uint32_t dB = sdB + s2 * GS_STAGE;
            size_t off = (size_t)(kt + 2) * 32;
            CP16(dA,           pA + off);
            CP16(dB,           pB + off);
            CP16(dB + 64 * 80, pB + off + (size_t)64 * GK);
            CPCOMMIT();
        }

        // kk = 0 MMAs
#pragma unroll
        for (int mt = 0; mt < 2; mt++)
#pragma unroll
            for (int nt = 0; nt < 4; nt++) mma_f32a(c[mt][nt], ah[mt], bb[nt]);

        // kk = 1 fragments + MMAs
#pragma unroll
        for (int mt = 0; mt < 2; mt++)
            ldsm4(ah[mt], stg + abase + mt * (16 * 80) + 32);
#pragma unroll
        for (int p = 0; p < 2; p++)
            ldsm4(&bb[2 * p][0], stg + bbase + p * (16 * 80) + 32);
#pragma unroll
        for (int mt = 0; mt < 2; mt++)
#pragma unroll
            for (int nt = 0; nt < 4; nt++) mma_f32a(c[mt][nt], ah[mt], bb[nt]);

        s = (s == 2) ? 0 : s + 1;
        s2 = (s2 == 2) ? 0 : s2 + 1;
    }
}

// ---------------------------------------------------------------------------
// gemm2: plain fp32-output GEMM (y @ w_proj -> out)
// ---------------------------------------------------------------------------
__global__ __launch_bounds__(256, 3) void hgemm1_kernel(
    const f16* __restrict__ A, const f16* __restrict__ B,
    float* __restrict__ C, int N)
{
    extern __shared__ char sm[];
    const uint32_t sb = smem_u32(sm);
    const int tid = threadIdx.x;
    const int lane = tid & 31, wid = tid >> 5;
    const int lg = lane >> 2, tq = lane & 3;
    const int mi = wid & 1, ni = wid >> 1;
    const size_t m0 = (size_t)blockIdx.y * 64, n0 = (size_t)blockIdx.x * 128;

    float c[2][4][4];
    gemm_mainloop(A, B, sm, sb, m0, n0, c);

#pragma unroll
    for (int mt = 0; mt < 2; mt++) {
        size_t r0 = m0 + mi * 32 + mt * 16 + lg;
#pragma unroll
        for (int nt = 0; nt < 4; nt++) {
            size_t col = n0 + ni * 32 + nt * 8 + tq * 2;
            *(float2*)(C + r0 * N + col) = make_float2(c[mt][nt][0], c[mt][nt][1]);
            *(float2*)(C + (r0 + 8) * N + col) = make_float2(c[mt][nt][2], c[mt][nt][3]);
        }
    }
}

// ---------------------------------------------------------------------------
// gemm1 fused: x @ w_attn with RoPE/V-transpose epilogue (R15).
// ---------------------------------------------------------------------------
__global__ __launch_bounds__(256, 3) void hgemm_qkv_kernel(
    const f16* __restrict__ A, const f16* __restrict__ B,
    const float* __restrict__ cosb, const float* __restrict__ sinb)
{
    extern __shared__ char sm[];
    const uint32_t sb = smem_u32(sm);
    const int tid = threadIdx.x;
    const int lane = tid & 31, wid = tid >> 5;
    const int lg = lane >> 2, tq = lane & 3;
    const int mi = wid & 1, ni = wid >> 1;
    const size_t m0 = (size_t)blockIdx.y * 64, n0 = (size_t)blockIdx.x * 128;

    float c[2][4][4];
    gemm_mainloop(A, B, sm, sb, m0, n0, c);

    __syncthreads();
    float* se = (float*)sm;                // [64][132]
#pragma unroll
    for (int mt = 0; mt < 2; mt++) {
        int row = mi * 32 + mt * 16 + lg;
#pragma unroll
        for (int nt = 0; nt < 4; nt++) {
            int col = ni * 32 + nt * 8 + tq * 2;
            se[row * 132 + col]           = c[mt][nt][0];
            se[row * 132 + col + 1]       = c[mt][nt][1];
            se[(row + 8) * 132 + col]     = c[mt][nt][2];
            se[(row + 8) * 132 + col + 1] = c[mt][nt][3];
        }
    }
    __syncthreads();

    const int grp = blockIdx.x / 6, slot = blockIdx.x % 6;
    const int b = (int)(m0 >> 11);
    const int tbase = (int)(m0 & (Tn - 1));

    if (slot < 5) {
        const float scale = (slot < 4) ? (float)QK_SCALE : 1.0f;
        f16* dst;
        size_t hb;
        if (slot < 4) { dst = g_qh; hb = (size_t)(b * 16 + grp * 4 + slot) * Tn; }
        else          { dst = g_kh; hb = (size_t)(b * 4 + grp) * Tn; }
#pragma unroll
        for (int it = 0; it < 16; it++) {
            int idx = it * 256 + tid;
            int d = idx & 63;
            int row = idx >> 6;
            int t = tbase + row;
            float x1 = se[row * 132 + d];
            float x2 = se[row * 132 + d + 64];
            float cc = cosb[t * 64 + d], ss = sinb[t * 64 + d];
            float o1 = (x1 * cc - x2 * ss) * scale;
            float o2 = (x1 * ss + x2 * cc) * scale;
            size_t base = (hb + t) * 128 + d;
            dst[base]      = __float2half_rn(o1);
            dst[base + 64] = __float2half_rn(o2);
        }
    } else {
        const size_t vb = (size_t)(b * 4 + grp) * 128;
#pragma unroll
        for (int it = 0; it < 8; it++) {
            int idx = it * 256 + tid;
            int d = idx >> 4;
            int tc = (idx & 15) * 4;
            uint32_t lo = pkh2(se[(tc + 0) * 132 + d], se[(tc + 1) * 132 + d]);
            uint32_t hi = pkh2(se[(tc + 2) * 132 + d], se[(tc + 3) * 132 + d]);
            *(uint2*)(g_vth + (vb + d) * Tn + tbase + tc) = make_uint2(lo, hi);
        }
    }
}

// ---------------------------------------------------------------------------
// Flash attention, plain fp16 inputs, f32 accumulate (unchanged).
// ---------------------------------------------------------------------------
#define AQ_H 0
#define AK_H 34816
#define AV_H 52224
#define ATT_SMEM 70656

__global__ __launch_bounds__(256, 1) void attn_kernel() {
    extern __shared__ char sm[];
    const uint32_t sb = smem_u32(sm);
    const int tid = threadIdx.x;
    const int lane = tid & 31, wid = tid >> 5;
    const int lg = lane >> 2, tq = lane & 3;
    const int qb = blockIdx.x, h = blockIdx.y, b = blockIdx.z;
    const int grp = h >> 2;

    const uint32_t qbase = sb + AQ_H + (wid * 16 + (lane & 15)) * 272 +
                           (lane >> 4) * 16;
    const uint32_t kbase = sb + AK_H + ((lane & 7) + ((lane >> 4) * 8)) * 272 +
                           ((lane >> 3) & 1) * 16;
    const uint32_t vbase = sb + AV_H + ((lane & 7) + ((lane >> 4) * 8)) * 144 +
                           ((lane >> 3) & 1) * 16;

    {
        const f16* qhp = g_qh + ((size_t)(b * 16 + h) * Tn + qb * 128) * 128;
#pragma unroll
        for (int it = 0; it < 8; it++) {
            int idx = it * 256 + tid;
            int r = idx >> 4, hx = idx & 15;
            *(uint4*)(sm + AQ_H + r * 272 + hx * 16) =
                *(const uint4*)(qhp + (size_t)r * 128 + hx * 8);
        }
    }

    float o[16][4];
#pragma unroll
    for (int i = 0; i < 16; i++)
#pragma unroll
        for (int j = 0; j < 4; j++) o[i][j] = 0.f;
    float m0 = __int_as_float(0xff800000), m1 = m0;
    float l0 = 0.f, l1 = 0.f;

    const f16* khp = g_kh + (size_t)(b * 4 + grp) * Tn * 128;
    const f16* vhp = g_vth + (size_t)(b * 4 + grp) * 128 * Tn;

#pragma unroll 1
    for (int kt = 0; kt < Tn / 64; kt++) {
        __syncthreads();
#pragma unroll
        for (int it = 0; it < 4; it++) {
            int idx = it * 256 + tid;
            int r = idx >> 4, hx = idx & 15;
            size_t go = ((size_t)kt * 64 + r) * 128 + hx * 8;
            *(uint4*)(sm + AK_H + r * 272 + hx * 16) = *(const uint4*)(khp + go);
        }
#pragma unroll
        for (int it = 0; it < 4; it++) {
            int idx = it * 256 + tid;
            int r = idx >> 3, hx = idx & 7;
            size_t go = (size_t)r * Tn + kt * 64 + hx * 8;
            *(uint4*)(sm + AV_H + r * 144 + hx * 16) = *(const uint4*)(vhp + go);
        }
        __syncthreads();

        float s[8][4];
#pragma unroll
        for (int i = 0; i < 8; i++)
#pragma unroll
            for (int j = 0; j < 4; j++) s[i][j] = 0.f;

#pragma unroll
        for (int kk = 0; kk < 8; kk++) {
            uint32_t qah[4];
            ldsm4(qah, qbase + kk * 32);
            uint32_t kb[8][2];
#pragma unroll
            for (int p = 0; p < 4; p++)
                ldsm4(&kb[2 * p][0], kbase + p * (16 * 272) + kk * 32);
#pragma unroll
            for (int nt = 0; nt < 8; nt++) mma_f32a(s[nt], qah, kb[nt]);
        }

        float mx0 = s[0][0], mx1 = s[0][2];
#pragma unroll
        for (int nt = 0; nt < 8; nt++) {
            mx0 = fmaxf(mx0, fmaxf(s[nt][0], s[nt][1]));
            mx1 = fmaxf(mx1, fmaxf(s[nt][2], s[nt][3]));
        }
        mx0 = fmaxf(mx0, __shfl_xor_sync(0xffffffffu, mx0, 1));
        mx0 = fmaxf(mx0, __shfl_xor_sync(0xffffffffu, mx0, 2));
        mx1 = fmaxf(mx1, __shfl_xor_sync(0xffffffffu, mx1, 1));
        mx1 = fmaxf(mx1, __shfl_xor_sync(0xffffffffu, mx1, 2));
        float mn0 = fmaxf(m0, mx0), mn1 = fmaxf(m1, mx1);
        float cr0 = ex2f(m0 - mn0), cr1 = ex2f(m1 - mn1);
        m0 = mn0; m1 = mn1;
        float sum0 = 0.f, sum1 = 0.f;
#pragma unroll
        for (int nt = 0; nt < 8; nt++) {
            s[nt][0] = ex2f(s[nt][0] - mn0);
            s[nt][1] = ex2f(s[nt][1] - mn0);
            s[nt][2] = ex2f(s[nt][2] - mn1);
            s[nt][3] = ex2f(s[nt][3] - mn1);
            sum0 += s[nt][0] + s[nt][1];
            sum1 += s[nt][2] + s[nt][3];
        }
        sum0 += __shfl_xor_sync(0xffffffffu, sum0, 1);
        sum0 += __shfl_xor_sync(0xffffffffu, sum0, 2);
        sum1 += __shfl_xor_sync(0xffffffffu, sum1, 1);
        sum1 += __shfl_xor_sync(0xffffffffu, sum1, 2);
        l0 = l0 * cr0 + sum0;
        l1 = l1 * cr1 + sum1;
#pragma unroll
        for (int nt = 0; nt < 16; nt++) {
            o[nt][0] *= cr0; o[nt][1] *= cr0;
            o[nt][2] *= cr1; o[nt][3] *= cr1;
        }

#pragma unroll
        for (int kk = 0; kk < 4; kk++) {
            uint32_t ph[4];
#pragma unroll
            for (int q2 = 0; q2 < 2; q2++) {
                ph[2 * q2]     = pkh2(s[2 * kk + q2][0], s[2 * kk + q2][1]);
                ph[2 * q2 + 1] = pkh2(s[2 * kk + q2][2], s[2 * kk + q2][3]);
            }
#pragma unroll
            for (int blk = 0; blk < 2; blk++) {
                uint32_t vb[8][2];
#pragma unroll
                for (int p = 0; p < 4; p++)
                    ldsm4(&vb[2 * p][0], vbase + (blk * 64 + p * 16) * 144 + kk * 32);
#pragma unroll
                for (int j = 0; j < 8; j++) mma_f32a(o[blk * 8 + j], ph, vb[j]);
            }
        }
    }

    float i0 = 1.f / l0, i1 = 1.f / l1;
    size_t row0 = (size_t)b * Tn + qb * 128 + wid * 16 + lg;
#pragma unroll
    for (int nt = 0; nt < 16; nt++) {
        int col = h * 128 + nt * 8 + tq * 2;
        *(uint32_t*)(g_yh + row0 * Cn + col) =
            pkh2(o[nt][0] * i0, o[nt][1] * i0);
        *(uint32_t*)(g_yh + (row0 + 8) * Cn + col) =
            pkh2(o[nt][2] * i1, o[nt][3] * i1);
    }
}

// ---------------------------------------------------------------------------
extern "C" void kernel_launch(void* const* d_in, const int* in_sizes, int n_in,
                              void* d_out, int out_size) {
    const float* x      = (const float*)d_in[0];
    const float* cosb   = (const float*)d_in[1];
    const float* sinb   = (const float*)d_in[2];
    const float* w_attn = (const float*)d_in[3];
    const float* w_proj = (const float*)d_in[4];
    float* out = (float*)d_out;
    (void)in_sizes; (void)n_in; (void)out_size;

    (void)cudaFuncSetAttribute(hgemm1_kernel,
                               cudaFuncAttributeMaxDynamicSharedMemorySize, GSM);
    (void)cudaFuncSetAttribute(hgemm_qkv_kernel,
                               cudaFuncAttributeMaxDynamicSharedMemorySize, GSM);
    (void)cudaFuncSetAttribute(attn_kernel,
                               cudaFuncAttributeMaxDynamicSharedMemorySize, ATT_SMEM);

    f16 *xh, *wah, *wph, *yh;
    (void)cudaGetSymbolAddress((void**)&xh, g_xh);
    (void)cudaGetSymbolAddress((void**)&wah, g_wah);
    (void)cudaGetSymbolAddress((void**)&wph, g_wph);
    (void)cudaGetSymbolAddress((void**)&yh, g_yh);

    // 0. merged prep: x->fp16, w_attn/w_proj transpose+cvt
    prep_kernel<<<18432, 256>>>(x, w_attn, w_proj);
    // 1. qkv = x @ w_attn, fused RoPE + v-transpose epilogue
    hgemm_qkv_kernel<<<dim3(QKVW / 128, ROWS / 64), 256, GSM>>>(xh, wah, cosb, sinb);
    // 2. attention -> yh
    attn_kernel<<<dim3(Tn / 128, 16, 2), 256, ATT_SMEM>>>();
    // 3. out = y @ w_proj
    hgemm1_kernel<<<dim3(Cn / 128, ROWS / 64), 256, GSM>>>(yh, wph, out, Cn);
}

// round 17
// speedup vs baseline: 1.2680x; 1.0055x over previous
#include <cuda_runtime.h>
#include <cuda_fp16.h>
#include <cstdint>
#include <cstddef>

// ---------------------------------------------------------------------------
// SelfAttention on sm_103, mma.sync fp16, fp32 accumulate everywhere.
// R17: prep store-coalescing fix. Weight transpose now uses 64x32 tiles with
// paired-row uint32 stores: each warp writes 128B contiguous (full line) vs
// 64B before, and fp32 reads are 128B/warp. x-conversion widened to uint4
// stores. Element-wise rounding identical -> rel_err stays 7.065852e-4.
// GEMMs (R16 reordered 3-stage ring) and attention untouched.
// ---------------------------------------------------------------------------

#define Tn     2048
#define Cn     2048
#define QKVW   3072          // (16 + 2*4) * 128
#define ROWS   4096          // B*T
#define GK     2048          // K dim of both big GEMMs

typedef __half f16;

__device__ __align__(16) f16  g_xh[(size_t)ROWS * GK];
__device__ __align__(16) f16  g_wah[(size_t)QKVW * GK];
__device__ __align__(16) f16  g_wph[(size_t)Cn * GK];
__device__ __align__(16) f16  g_qh[(size_t)2 * 16 * Tn * 128];
__device__ __align__(16) f16  g_kh[(size_t)2 * 4 * Tn * 128];
__device__ __align__(16) f16  g_vth[(size_t)2 * 4 * 128 * Tn];
__device__ __align__(16) f16  g_yh[(size_t)ROWS * Cn];

// 1/sqrt(128) * log2(e): softmax scale + exp->exp2, folded into q
#define QK_SCALE (0.08838834764831845f * 1.4426950408889634f)

// ============================ helpers =======================================
__device__ __forceinline__ float ex2f(float x) {
    float r;
    asm("ex2.approx.ftz.f32 %0, %1;" : "=f"(r) : "f"(x));
    return r;
}
__device__ __forceinline__ uint32_t pkh2(float lo, float hi) {
    __half2 h = __floats2half2_rn(lo, hi);
    return *reinterpret_cast<uint32_t*>(&h);
}
__device__ __forceinline__ void mma_f32a(float (&d)[4], const uint32_t (&a)[4],
                                         const uint32_t* b) {
    asm volatile(
        "mma.sync.aligned.m16n8k16.row.col.f32.f16.f16.f32 "
        "{%0,%1,%2,%3}, {%4,%5,%6,%7}, {%8,%9}, {%0,%1,%2,%3};"
        : "+f"(d[0]), "+f"(d[1]), "+f"(d[2]), "+f"(d[3])
        : "r"(a[0]), "r"(a[1]), "r"(a[2]), "r"(a[3]), "r"(b[0]), "r"(b[1]));
}
__device__ __forceinline__ void ldsm4(uint32_t* r, uint32_t a) {
    asm volatile("ldmatrix.sync.aligned.m8n8.x4.shared.b16 {%0,%1,%2,%3}, [%4];"
                 : "=r"(r[0]), "=r"(r[1]), "=r"(r[2]), "=r"(r[3]) : "r"(a));
}
__device__ __forceinline__ uint32_t smem_u32(const void* p) {
    uint32_t a;
    asm("{ .reg .u64 t; cvta.to.shared.u64 t, %1; cvt.u32.u64 %0, t; }"
        : "=r"(a) : "l"(p));
    return a;
}
#define CP16(dst, src) \
    asm volatile("cp.async.cg.shared.global [%0], [%1], 16;" \
                 :: "r"(dst), "l"(src) : "memory")
#define CPCOMMIT() asm volatile("cp.async.commit_group;" ::: "memory")
#define CPWAIT1()  asm volatile("cp.async.wait_group 1;" ::: "memory")
#define CPWAIT0()  asm volatile("cp.async.wait_group 0;" ::: "memory")

// ---------------------------------------------------------------------------
// merged prep:
//   [0, 4096)          x -> fp16 (uint4 stores, 8 floats/thread)
//   [4096, 4096+3072)  w_attn transpose+cvt, 64x32 tiles, uint32 stores
//   [7168, 9216)       w_proj  transpose+cvt, 64x32 tiles, uint32 stores
// ---------------------------------------------------------------------------
__global__ __launch_bounds__(256) void prep_kernel(
    const float* __restrict__ x,
    const float* __restrict__ wa,
    const float* __restrict__ wp)
{
    __shared__ float tb[64][33];
    const int tid = threadIdx.x;
    const int bx = blockIdx.x;

    if (bx < 4096) {
        size_t i = ((size_t)bx * 256 + tid) * 8;
        float4 v0 = *(const float4*)(x + i);
        float4 v1 = *(const float4*)(x + i + 4);
        uint4 o;
        o.x = pkh2(v0.x, v0.y);
        o.y = pkh2(v0.z, v0.w);
        o.z = pkh2(v1.x, v1.y);
        o.w = pkh2(v1.z, v1.w);
        *(uint4*)(g_xh + i) = o;
        return;
    }

    const float* in;
    f16* hi;
    int Ccols, cx, cy;
    if (bx < 4096 + 3072) {
        int t = bx - 4096;
        in = wa; hi = g_wah; Ccols = QKVW;
        cx = t % 96; cy = t / 96;          // 96 col-tiles x 32 row-tiles
    } else {
        int t = bx - 7168;
        in = wp; hi = g_wph; Ccols = Cn;
        cx = t % 64; cy = t / 64;          // 64 col-tiles x 32 row-tiles
    }
    const int bxo = cx * 32;               // input col offset (output major)
    const int byo = cy * 64;               // input row offset (output minor)
    const int tx = tid & 31, ty = tid >> 5;

    // load 64 rows x 32 cols fp32 (128B per warp-row)
#pragma unroll
    for (int j = 0; j < 64; j += 8)
        tb[ty + j][tx] = in[(size_t)(byo + ty + j) * Ccols + bxo + tx];
    __syncthreads();

    // write transposed fp16, paired rows -> uint32; warp covers 128B/col
    const int rp = tid & 31;
    const int cb = tid >> 5;
#pragma unroll
    for (int p = 0; p < 4; p++) {
        int c = p * 8 + cb;
        uint32_t val = pkh2(tb[2 * rp][c], tb[2 * rp + 1][c]);
        *(uint32_t*)(hi + (size_t)(bxo + c) * GK + byo + 2 * rp) = val;
    }
}

// ============================================================================
// GEMM mainloop (R16): 64x128 tile, kchunk 32, 3-stage cp.async ring,
// kk=0 fragments loaded before next-stage cp.async issue.
// ============================================================================
#define GS_STAGE 15360
#define GSM (3 * GS_STAGE)

__device__ __forceinline__ void gemm_mainloop(
    const f16* __restrict__ A, const f16* __restrict__ B,
    char* sm, uint32_t sb, size_t m0, size_t n0, float (&c)[2][4][4])
{
    const int tid = threadIdx.x;
    const int lane = tid & 31, wid = tid >> 5;
    const int mi = wid & 1, ni = wid >> 1;

    const uint32_t abase =
        (uint32_t)((mi * 32 + (lane & 15)) * 80 + (lane >> 4) * 16);
    const uint32_t bbase =
        (uint32_t)(5120 + (ni * 32 + (lane & 7) + ((lane >> 4) * 8)) * 80 +
                   ((lane >> 3) & 1) * 16);

    const int ar = tid >> 2;
    const int ac = tid & 3;
    const f16* pA = A + (m0 + ar) * GK + ac * 8;
    const f16* pB = B + (n0 + ar) * GK + ac * 8;
    const uint32_t sdA = sb + ar * 80 + ac * 16;
    const uint32_t sdB = sb + 5120 + ar * 80 + ac * 16;

#pragma unroll
    for (int a = 0; a < 2; a++)
#pragma unroll
        for (int b = 0; b < 4; b++)
#pragma unroll
            for (int d = 0; d < 4; d++) c[a][b][d] = 0.f;

    const int NT = GK / 32;

#pragma unroll
    for (int p = 0; p < 2; p++) {
        uint32_t dA = sdA + p * GS_STAGE;
        uint32_t dB = sdB + p * GS_STAGE;
        size_t off = (size_t)p * 32;
        CP16(dA,           pA + off);
        CP16(dB,           pB + off);
        CP16(dB + 64 * 80, pB + off + (size_t)64 * GK);
        CPCOMMIT();
    }

    int s = 0, s2 = 2;
#pragma unroll 1
    for (int kt = 0; kt < NT; kt++) {
        if (kt == NT - 1) { CPWAIT0(); } else { CPWAIT1(); }
        __syncthreads();

        const uint32_t stg = sb + s * GS_STAGE;

        uint32_t ah[2][4], bb[4][2];
#pragma unroll
        for (int mt = 0; mt < 2; mt++)
            ldsm4(ah[mt], stg + abase + mt * (16 * 80));
#pragma unroll
        for (int p = 0; p < 2; p++)
            ldsm4(&bb[2 * p][0], stg + bbase + p * (16 * 80));

        if (kt + 2 < NT) {
            uint32_t dA = sdA + s2 * GS_STAGE;
            uint32_t dB = sdB + s2 * GS_STAGE;
            size_t off = (size_t)(kt + 2) * 32;
            CP16(dA,           pA + off);
            CP16(dB,           pB + off);
            CP16(dB + 64 * 80, pB + off + (size_t)64 * GK);
            CPCOMMIT();
        }

#pragma unroll
        for (int mt = 0; mt < 2; mt++)
#pragma unroll
            for (int nt = 0; nt < 4; nt++) mma_f32a(c[mt][nt], ah[mt], bb[nt]);

#pragma unroll
        for (int mt = 0; mt < 2; mt++)
            ldsm4(ah[mt], stg + abase + mt * (16 * 80) + 32);
#pragma unroll
        for (int p = 0; p < 2; p++)
            ldsm4(&bb[2 * p][0], stg + bbase + p * (16 * 80) + 32);
#pragma unroll
        for (int mt = 0; mt < 2; mt++)
#pragma unroll
            for (int nt = 0; nt < 4; nt++) mma_f32a(c[mt][nt], ah[mt], bb[nt]);

        s = (s == 2) ? 0 : s + 1;
        s2 = (s2 == 2) ? 0 : s2 + 1;
    }
}

// ---------------------------------------------------------------------------
// gemm2: plain fp32-output GEMM (y @ w_proj -> out)
// ---------------------------------------------------------------------------
__global__ __launch_bounds__(256, 3) void hgemm1_kernel(
    const f16* __restrict__ A, const f16* __restrict__ B,
    float* __restrict__ C, int N)
{
    extern __shared__ char sm[];
    const uint32_t sb = smem_u32(sm);
    const int tid = threadIdx.x;
    const int lane = tid & 31, wid = tid >> 5;
    const int lg = lane >> 2, tq = lane & 3;
    const int mi = wid & 1, ni = wid >> 1;
    const size_t m0 = (size_t)blockIdx.y * 64, n0 = (size_t)blockIdx.x * 128;

    float c[2][4][4];
    gemm_mainloop(A, B, sm, sb, m0, n0, c);

#pragma unroll
    for (int mt = 0; mt < 2; mt++) {
        size_t r0 = m0 + mi * 32 + mt * 16 + lg;
#pragma unroll
        for (int nt = 0; nt < 4; nt++) {
            size_t col = n0 + ni * 32 + nt * 8 + tq * 2;
            *(float2*)(C + r0 * N + col) = make_float2(c[mt][nt][0], c[mt][nt][1]);
            *(float2*)(C + (r0 + 8) * N + col) = make_float2(c[mt][nt][2], c[mt][nt][3]);
        }
    }
}

// ---------------------------------------------------------------------------
// gemm1 fused: x @ w_attn with RoPE/V-transpose epilogue (R15).
// ---------------------------------------------------------------------------
__global__ __launch_bounds__(256, 3) void hgemm_qkv_kernel(
    const f16* __restrict__ A, const f16* __restrict__ B,
    const float* __restrict__ cosb, const float* __restrict__ sinb)
{
    extern __shared__ char sm[];
    const uint32_t sb = smem_u32(sm);
    const int tid = threadIdx.x;
    const int lane = tid & 31, wid = tid >> 5;
    const int lg = lane >> 2, tq = lane & 3;
    const int mi = wid & 1, ni = wid >> 1;
    const size_t m0 = (size_t)blockIdx.y * 64, n0 = (size_t)blockIdx.x * 128;

    float c[2][4][4];
    gemm_mainloop(A, B, sm, sb, m0, n0, c);

    __syncthreads();
    float* se = (float*)sm;                // [64][132]
#pragma unroll
    for (int mt = 0; mt < 2; mt++) {
        int row = mi * 32 + mt * 16 + lg;
#pragma unroll
        for (int nt = 0; nt < 4; nt++) {
            int col = ni * 32 + nt * 8 + tq * 2;
            se[row * 132 + col]           = c[mt][nt][0];
            se[row * 132 + col + 1]       = c[mt][nt][1];
            se[(row + 8) * 132 + col]     = c[mt][nt][2];
            se[(row + 8) * 132 + col + 1] = c[mt][nt][3];
        }
    }
    __syncthreads();

    const int grp = blockIdx.x / 6, slot = blockIdx.x % 6;
    const int b = (int)(m0 >> 11);
    const int tbase = (int)(m0 & (Tn - 1));

    if (slot < 5) {
        const float scale = (slot < 4) ? (float)QK_SCALE : 1.0f;
        f16* dst;
        size_t hb;
        if (slot < 4) { dst = g_qh; hb = (size_t)(b * 16 + grp * 4 + slot) * Tn; }
        else          { dst = g_kh; hb = (size_t)(b * 4 + grp) * Tn; }
#pragma unroll
        for (int it = 0; it < 16; it++) {
            int idx = it * 256 + tid;
            int d = idx & 63;
            int row = idx >> 6;
            int t = tbase + row;
            float x1 = se[row * 132 + d];
            float x2 = se[row * 132 + d + 64];
            float cc = cosb[t * 64 + d], ss = sinb[t * 64 + d];
            float o1 = (x1 * cc - x2 * ss) * scale;
            float o2 = (x1 * ss + x2 * cc) * scale;
            size_t base = (hb + t) * 128 + d;
            dst[base]      = __float2half_rn(o1);
            dst[base + 64] = __float2half_rn(o2);
        }
    } else {
        const size_t vb = (size_t)(b * 4 + grp) * 128;
#pragma unroll
        for (int it = 0; it < 8; it++) {
            int idx = it * 256 + tid;
            int d = idx >> 4;
            int tc = (idx & 15) * 4;
            uint32_t lo = pkh2(se[(tc + 0) * 132 + d], se[(tc + 1) * 132 + d]);
            uint32_t hi = pkh2(se[(tc + 2) * 132 + d], se[(tc + 3) * 132 + d]);
            *(uint2*)(g_vth + (vb + d) * Tn + tbase + tc) = make_uint2(lo, hi);
        }
    }
}

// ---------------------------------------------------------------------------
// Flash attention, plain fp16 inputs, f32 accumulate (unchanged).
// ---------------------------------------------------------------------------
#define AQ_H 0
#define AK_H 34816
#define AV_H 52224
#define ATT_SMEM 70656

__global__ __launch_bounds__(256, 1) void attn_kernel() {
    extern __shared__ char sm[];
    const uint32_t sb = smem_u32(sm);
    const int tid = threadIdx.x;
    const int lane = tid & 31, wid = tid >> 5;
    const int lg = lane >> 2, tq = lane & 3;
    const int qb = blockIdx.x, h = blockIdx.y, b = blockIdx.z;
    const int grp = h >> 2;

    const uint32_t qbase = sb + AQ_H + (wid * 16 + (lane & 15)) * 272 +
                           (lane >> 4) * 16;
    const uint32_t kbase = sb + AK_H + ((lane & 7) + ((lane >> 4) * 8)) * 272 +
                           ((lane >> 3) & 1) * 16;
    const uint32_t vbase = sb + AV_H + ((lane & 7) + ((lane >> 4) * 8)) * 144 +
                           ((lane >> 3) & 1) * 16;

    {
        const f16* qhp = g_qh + ((size_t)(b * 16 + h) * Tn + qb * 128) * 128;
#pragma unroll
        for (int it = 0; it < 8; it++) {
            int idx = it * 256 + tid;
            int r = idx >> 4, hx = idx & 15;
            *(uint4*)(sm + AQ_H + r * 272 + hx * 16) =
                *(const uint4*)(qhp + (size_t)r * 128 + hx * 8);
        }
    }

    float o[16][4];
#pragma unroll
    for (int i = 0; i < 16; i++)
#pragma unroll
        for (int j = 0; j < 4; j++) o[i][j] = 0.f;
    float m0 = __int_as_float(0xff800000), m1 = m0;
    float l0 = 0.f, l1 = 0.f;

    const f16* khp = g_kh + (size_t)(b * 4 + grp) * Tn * 128;
    const f16* vhp = g_vth + (size_t)(b * 4 + grp) * 128 * Tn;

#pragma unroll 1
    for (int kt = 0; kt < Tn / 64; kt++) {
        __syncthreads();
#pragma unroll
        for (int it = 0; it < 4; it++) {
            int idx = it * 256 + tid;
            int r = idx >> 4, hx = idx & 15;
            size_t go = ((size_t)kt * 64 + r) * 128 + hx * 8;
            *(uint4*)(sm + AK_H + r * 272 + hx * 16) = *(const uint4*)(khp + go);
        }
#pragma unroll
        for (int it = 0; it < 4; it++) {
            int idx = it * 256 + tid;
            int r = idx >> 3, hx = idx & 7;
            size_t go = (size_t)r * Tn + kt * 64 + hx * 8;
            *(uint4*)(sm + AV_H + r * 144 + hx * 16) = *(const uint4*)(vhp + go);
        }
        __syncthreads();

        float s[8][4];
#pragma unroll
        for (int i = 0; i < 8; i++)
#pragma unroll
            for (int j = 0; j < 4; j++) s[i][j] = 0.f;

#pragma unroll
        for (int kk = 0; kk < 8; kk++) {
            uint32_t qah[4];
            ldsm4(qah, qbase + kk * 32);
            uint32_t kb[8][2];
#pragma unroll
            for (int p = 0; p < 4; p++)
                ldsm4(&kb[2 * p][0], kbase + p * (16 * 272) + kk * 32);
#pragma unroll
            for (int nt = 0; nt < 8; nt++) mma_f32a(s[nt], qah, kb[nt]);
        }

        float mx0 = s[0][0], mx1 = s[0][2];
#pragma unroll
        for (int nt = 0; nt < 8; nt++) {
            mx0 = fmaxf(mx0, fmaxf(s[nt][0], s[nt][1]));
            mx1 = fmaxf(mx1, fmaxf(s[nt][2], s[nt][3]));
        }
        mx0 = fmaxf(mx0, __shfl_xor_sync(0xffffffffu, mx0, 1));
        mx0 = fmaxf(mx0, __shfl_xor_sync(0xffffffffu, mx0, 2));
        mx1 = fmaxf(mx1, __shfl_xor_sync(0xffffffffu, mx1, 1));
        mx1 = fmaxf(mx1, __shfl_xor_sync(0xffffffffu, mx1, 2));
        float mn0 = fmaxf(m0, mx0), mn1 = fmaxf(m1, mx1);
        float cr0 = ex2f(m0 - mn0), cr1 = ex2f(m1 - mn1);
        m0 = mn0; m1 = mn1;
        float sum0 = 0.f, sum1 = 0.f;
#pragma unroll
        for (int nt = 0; nt < 8; nt++) {
            s[nt][0] = ex2f(s[nt][0] - mn0);
            s[nt][1] = ex2f(s[nt][1] - mn0);
            s[nt][2] = ex2f(s[nt][2] - mn1);
            s[nt][3] = ex2f(s[nt][3] - mn1);
            sum0 += s[nt][0] + s[nt][1];
            sum1 += s[nt][2] + s[nt][3];
        }
        sum0 += __shfl_xor_sync(0xffffffffu, sum0, 1);
        sum0 += __shfl_xor_sync(0xffffffffu, sum0, 2);
        sum1 += __shfl_xor_sync(0xffffffffu, sum1, 1);
        sum1 += __shfl_xor_sync(0xffffffffu, sum1, 2);
        l0 = l0 * cr0 + sum0;
        l1 = l1 * cr1 + sum1;
#pragma unroll
        for (int nt = 0; nt < 16; nt++) {
            o[nt][0] *= cr0; o[nt][1] *= cr0;
            o[nt][2] *= cr1; o[nt][3] *= cr1;
        }

#pragma unroll
        for (int kk = 0; kk < 4; kk++) {
            uint32_t ph[4];
#pragma unroll
            for (int q2 = 0; q2 < 2; q2++) {
                ph[2 * q2]     = pkh2(s[2 * kk + q2][0], s[2 * kk + q2][1]);
                ph[2 * q2 + 1] = pkh2(s[2 * kk + q2][2], s[2 * kk + q2][3]);
            }
#pragma unroll
            for (int blk = 0; blk < 2; blk++) {
                uint32_t vb[8][2];
#pragma unroll
                for (int p = 0; p < 4; p++)
                    ldsm4(&vb[2 * p][0], vbase + (blk * 64 + p * 16) * 144 + kk * 32);
#pragma unroll
                for (int j = 0; j < 8; j++) mma_f32a(o[blk * 8 + j], ph, vb[j]);
            }
        }
    }

    float i0 = 1.f / l0, i1 = 1.f / l1;
    size_t row0 = (size_t)b * Tn + qb * 128 + wid * 16 + lg;
#pragma unroll
    for (int nt = 0; nt < 16; nt++) {
        int col = h * 128 + nt * 8 + tq * 2;
        *(uint32_t*)(g_yh + row0 * Cn + col) =
            pkh2(o[nt][0] * i0, o[nt][1] * i0);
        *(uint32_t*)(g_yh + (row0 + 8) * Cn + col) =
            pkh2(o[nt][2] * i1, o[nt][3] * i1);
    }
}

// ---------------------------------------------------------------------------
extern "C" void kernel_launch(void* const* d_in, const int* in_sizes, int n_in,
                              void* d_out, int out_size) {
    const float* x      = (const float*)d_in[0];
    const float* cosb   = (const float*)d_in[1];
    const float* sinb   = (const float*)d_in[2];
    const float* w_attn = (const float*)d_in[3];
    const float* w_proj = (const float*)d_in[4];
    float* out = (float*)d_out;
    (void)in_sizes; (void)n_in; (void)out_size;

    (void)cudaFuncSetAttribute(hgemm1_kernel,
                               cudaFuncAttributeMaxDynamicSharedMemorySize, GSM);
    (void)cudaFuncSetAttribute(hgemm_qkv_kernel,
                               cudaFuncAttributeMaxDynamicSharedMemorySize, GSM);
    (void)cudaFuncSetAttribute(attn_kernel,
                               cudaFuncAttributeMaxDynamicSharedMemorySize, ATT_SMEM);

    f16 *xh, *wah, *wph, *yh;
    (void)cudaGetSymbolAddress((void**)&xh, g_xh);
    (void)cudaGetSymbolAddress((void**)&wah, g_wah);
    (void)cudaGetSymbolAddress((void**)&wph, g_wph);
    (void)cudaGetSymbolAddress((void**)&yh, g_yh);

    // 0. merged prep: x->fp16, w_attn/w_proj transpose+cvt (vectorized stores)
    prep_kernel<<<9216, 256>>>(x, w_attn, w_proj);
    // 1. qkv = x @ w_attn, fused RoPE + v-transpose epilogue
    hgemm_qkv_kernel<<<dim3(QKVW / 128, ROWS / 64), 256, GSM>>>(xh, wah, cosb, sinb);
    // 2. attention -> yh
    attn_kernel<<<dim3(Tn / 128, 16, 2), 256, ATT_SMEM>>>();
    // 3. out = y @ w_proj
    hgemm1_kernel<<<dim3(Cn / 128, ROWS / 64), 256, GSM>>>(yh, wph, out, Cn);
}